// round 12
// baseline (speedup 1.0000x reference)
#include <cuda_runtime.h>
#include <cstdint>

#define N_NODES 50000
#define N_EDGES 800000
#define DNODE   128
#define DEDGE   32
#define HID     128

typedef unsigned long long u64;

// ---------------- device-global scratch (no allocations allowed) ----------------
__device__ int   g_src[N_EDGES];
__device__ int   g_dst[N_EDGES];
__device__ float g_mi[(size_t)N_NODES * HID];      // 25.6 MB scatter target
__device__ float g_P[(size_t)N_NODES * 256];       // 51.2 MB: [h@W1a | h@W1b]
__device__ float g_W1r[288 * 128];                 // We1, tf32-rounded (RNA), [K][N]
__device__ float g_W2r[128 * 128];                 // We2, tf32-rounded (RNA), [K][N]
__device__ float g_Wh1hi[256 * 128];               // Wh1 split hi/lo (3xTF32)
__device__ float g_Wh1lo[256 * 128];
__device__ float g_Wh2hi[128 * 128];
__device__ float g_Wh2lo[128 * 128];

// ---------------- helpers ----------------
__device__ __forceinline__ uint32_t smem_u32(const void* p) {
    uint32_t a;
    asm("{ .reg .u64 t; cvta.to.shared.u64 t, %1; cvt.u32.u64 %0, t; }" : "=r"(a) : "l"(p));
    return a;
}
__device__ __forceinline__ uint32_t rna(float x) {
    uint32_t r; asm("cvt.rna.tf32.f32 %0, %1;" : "=r"(r) : "f"(x)); return r;
}

#define CP_ASYNC(ds, gp) \
    asm volatile("cp.async.cg.shared.global [%0], [%1], 16;" :: "r"(ds), "l"(gp))
#define CP_COMMIT() asm volatile("cp.async.commit_group;" ::: "memory")
#define CP_WAIT1()  asm volatile("cp.async.wait_group 1;" ::: "memory")
#define CP_WAIT0()  asm volatile("cp.async.wait_group 0;" ::: "memory")

#define MMA_TF32(C, a0, a1, a2, a3, b0, b1) \
    asm volatile("mma.sync.aligned.m16n8k8.row.col.f32.tf32.tf32.f32 " \
        "{%0,%1,%2,%3}, {%4,%5,%6,%7}, {%8,%9}, {%0,%1,%2,%3};" \
        : "+f"((C)[0]), "+f"((C)[1]), "+f"((C)[2]), "+f"((C)[3]) \
        : "r"(a0), "r"(a1), "r"(a2), "r"(a3), "r"(b0), "r"(b1))

// ---------------- aux kernel: dtype-detect + index convert + zero g_mi ----------------
__global__ void convert_kernel(const void* __restrict__ ei) {
    __shared__ int s64;
    if (threadIdx.x == 0) {
        const int* p = (const int*)ei;
        int all0 = 1;
        for (int s = 0; s < 256; s++)
            if (p[2 * s + 1] != 0) { all0 = 0; break; }
        s64 = all0;
    }
    __syncthreads();
    int i = blockIdx.x * blockDim.x + threadIdx.x;
    if (i < N_EDGES) {
        if (s64) {
            const long long* p = (const long long*)ei;
            g_src[i] = (int)p[i];
            g_dst[i] = (int)p[N_EDGES + i];
        } else {
            const int* p = (const int*)ei;
            g_src[i] = p[i];
            g_dst[i] = p[N_EDGES + i];
        }
    }
    size_t n4 = (size_t)N_NODES * HID / 4;
    float4 z = make_float4(0.f, 0.f, 0.f, 0.f);
    for (size_t j = (size_t)blockIdx.x * blockDim.x + threadIdx.x; j < n4;
         j += (size_t)gridDim.x * blockDim.x)
        ((float4*)g_mi)[j] = z;
}

// ---------------- prep: RNA-round edge weights, split node weights hi/lo ----------------
__global__ void prep_kernel(const float* __restrict__ W1, const float* __restrict__ W2,
                            const float* __restrict__ Wh1, const float* __restrict__ Wh2) {
    int t = blockIdx.x * blockDim.x + threadIdx.x;
    int stride = gridDim.x * blockDim.x;
    for (int i = t; i < 288 * 128; i += stride)
        g_W1r[i] = __uint_as_float(rna(W1[i]));
    for (int i = t; i < 128 * 128; i += stride)
        g_W2r[i] = __uint_as_float(rna(W2[i]));
    for (int i = t; i < 256 * 128; i += stride) {
        float w = Wh1[i];
        uint32_t hi = rna(w);
        g_Wh1hi[i] = __uint_as_float(hi);
        g_Wh1lo[i] = __uint_as_float(rna(w - __uint_as_float(hi)));
    }
    for (int i = t; i < 128 * 128; i += stride) {
        float w = Wh2[i];
        uint32_t hi = rna(w);
        g_Wh2hi[i] = __uint_as_float(hi);
        g_Wh2lo[i] = __uint_as_float(rna(w - __uint_as_float(hi)));
    }
}

// =================================================================
// Precompute P = h @ [We1_a | We1_b]  (50k x 128 x 256, tf32 mma)
// =================================================================
#define GP_SMEM 98304

__global__ __launch_bounds__(256) void gemm_P(const float* __restrict__ h) {
    extern __shared__ char sm[];
    const uint32_t smb = smem_u32(sm);
    const int tid = threadIdx.x, lane = tid & 31, wid = tid >> 5;
    const int g = lane >> 2, t4 = lane & 3;
    const int m0 = (wid >> 2) * 64, n0 = (wid & 3) * 64;
    const int r0 = blockIdx.x * 128;

    auto issue_x = [&](int ch, int b) {
        uint32_t xb = smb + b * 16384;
#pragma unroll
        for (int i = 0; i < 4; i++) {
            int f = tid + i * 256;
            int row = f >> 3, q = f & 7;
            int gr = r0 + row; if (gr >= N_NODES) gr = 0;
            const float* gp = h + (size_t)gr * DNODE + ch * 32 + q * 4;
            uint32_t ds = xb + 4u * (uint32_t)(row * 32 + ((4 * q) ^ (4 * (row & 7))));
            CP_ASYNC(ds, gp);
        }
    };
    auto issue_w = [&](int ch, int b) {
        uint32_t wb = smb + 32768 + b * 32768;
#pragma unroll
        for (int i = 0; i < 8; i++) {
            int f = tid + i * 256;
            int k = f >> 6, n4 = f & 63;
            int n = 4 * n4;
            const float* gp = (n < 128)
                ? g_W1r + (size_t)(ch * 32 + k) * 128 + n
                : g_W1r + (size_t)(128 + ch * 32 + k) * 128 + (n - 128);
            uint32_t ds = wb + 4u * (uint32_t)(k * 256 + (n ^ (8 * (k & 3))));
            CP_ASYNC(ds, gp);
        }
    };

    float c[4][8][4];
#pragma unroll
    for (int mf = 0; mf < 4; mf++)
#pragma unroll
        for (int nf = 0; nf < 8; nf++)
#pragma unroll
            for (int j = 0; j < 4; j++) c[mf][nf][j] = 0.0f;

    issue_x(0, 0); issue_w(0, 0); CP_COMMIT();
    for (int ch = 0; ch < 4; ch++) {
        CP_WAIT0();
        __syncthreads();
        if (ch < 3) {
            issue_x(ch + 1, (ch + 1) & 1);
            issue_w(ch + 1, (ch + 1) & 1);
            CP_COMMIT();
        }
        const uint32_t* Xw = (const uint32_t*)sm + (ch & 1) * 4096;
        const uint32_t* Ww = (const uint32_t*)(sm + 32768) + (ch & 1) * 8192;
#pragma unroll
        for (int s = 0; s < 4; s++) {
            const int kb = 8 * s + t4;
            uint32_t b0r[8], b1r[8];
#pragma unroll
            for (int nf = 0; nf < 8; nf++) {
                int wc = (n0 + 8 * nf + g) ^ (8 * t4);
                b0r[nf] = Ww[kb * 256 + wc];
                b1r[nf] = Ww[(kb + 4) * 256 + wc];
            }
#pragma unroll
            for (int mf = 0; mf < 4; mf++) {
                int base = (m0 + mf * 16 + g) * 32;
                uint32_t a0 = Xw[base + (kb ^ (4 * g))];
                uint32_t a1 = Xw[base + 8 * 32 + (kb ^ (4 * g))];
                uint32_t a2 = Xw[base + ((kb + 4) ^ (4 * g))];
                uint32_t a3 = Xw[base + 8 * 32 + ((kb + 4) ^ (4 * g))];
#pragma unroll
                for (int nf = 0; nf < 8; nf++)
                    MMA_TF32(c[mf][nf], a0, a1, a2, a3, b0r[nf], b1r[nf]);
            }
        }
    }

#pragma unroll
    for (int mf = 0; mf < 4; mf++) {
        int r = m0 + mf * 16 + g;
#pragma unroll
        for (int nf = 0; nf < 8; nf++) {
            int col = n0 + 8 * nf + 2 * t4;
            if (r0 + r < N_NODES)
                *(float2*)(g_P + (size_t)(r0 + r) * 256 + col) =
                    make_float2(c[mf][nf][0], c[mf][nf][1]);
            if (r0 + r + 8 < N_NODES)
                *(float2*)(g_P + (size_t)(r0 + r + 8) * 256 + col) =
                    make_float2(c[mf][nf][2], c[mf][nf][3]);
        }
    }
}

// =================================================================
// Edge kernel v8: 256 edges/block, 64x64 warp tiles (B-reuse 4),
// R11 lean schedule. 1 CTA/SM.
// smem map (bytes):
//   [0, 131072)       Ys: 256 rows x 128 words (ea X overlays [0,32768))
//   [131072, 163840)  Wbuf0/Wbuf1 (16 KB each)
//   sb1@163840  sb2@164352  sSrc@164864  sDst@165888
// =================================================================
#define EDGE_SMEM 166912

__global__ __launch_bounds__(256, 1) void edge_kernel_m(
    const float* __restrict__ ea,
    const float* __restrict__ b1g, const float* __restrict__ b2g)
{
    extern __shared__ char sm[];
    const uint32_t smb = smem_u32(sm);
    float* Ys  = (float*)sm;
    float* sb1 = (float*)(sm + 163840);
    float* sb2 = (float*)(sm + 164352);
    int*   sSrc = (int*)(sm + 164864);
    int*   sDst = (int*)(sm + 165888);

    const int tid  = threadIdx.x;
    const int lane = tid & 31, wid = tid >> 5;
    const int g    = lane >> 2, t4 = lane & 3;
    const int m0   = (wid >> 1) * 64;     // 4 m-warps x 64 rows
    const int n0   = (wid & 1) * 64;      // 2 n-warps x 64 cols
    const int e0   = blockIdx.x * 256;

    if (tid < 128) { sb1[tid] = b1g[tid]; sb2[tid] = b2g[tid]; }
    sSrc[tid] = g_src[e0 + tid];
    sDst[tid] = g_dst[e0 + tid];

    auto issue_w = [&](const float* W, int ch, int wb) {
        uint32_t wbase = smb + 131072 + wb * 16384;
#pragma unroll
        for (int i = 0; i < 4; i++) {
            int f = tid + i * 256;
            int k = f >> 5, n4 = f & 31;
            const float* gp = W + (size_t)(ch * 32 + k) * 128 + n4 * 4;
            uint32_t ds = wbase + 4u * (uint32_t)(k * 128 + ((4 * n4) ^ (8 * (k & 3))));
            CP_ASYNC(ds, gp);
        }
    };

    // group A: ea chunk (256 rows x 32 floats) + W1e (buf0)
#pragma unroll
    for (int i = 0; i < 8; i++) {
        int f = tid + i * 256;
        int row = f >> 3, q = f & 7;
        const float* gp = ea + (size_t)(e0 + row) * DEDGE + q * 4;
        uint32_t ds = smb + 4u * (uint32_t)(row * 32 + ((4 * q) ^ (4 * (row & 7))));
        CP_ASYNC(ds, gp);
    }
    issue_w(g_W1r, 8, 0);
    CP_COMMIT();
    // group B: W2 chunk0 -> buf1 (prefetched across phase 1 + merge)
    issue_w(g_W2r, 0, 1);
    CP_COMMIT();

    float c[4][8][4];
#pragma unroll
    for (int mf = 0; mf < 4; mf++)
#pragma unroll
        for (int nf = 0; nf < 8; nf++)
#pragma unroll
            for (int j = 0; j < 4; j++) c[mf][nf][j] = 0.0f;

    auto compute = [&](const uint32_t* Xw, int rstride, int cofs, const uint32_t* Ww) {
#pragma unroll
        for (int s = 0; s < 4; s++) {
            const int kb = 8 * s + t4;
            uint32_t b0r[8], b1r[8];
#pragma unroll
            for (int nf = 0; nf < 8; nf++) {
                int wc = (n0 + 8 * nf + g) ^ (8 * t4);
                b0r[nf] = Ww[kb * 128 + wc];
                b1r[nf] = Ww[(kb + 4) * 128 + wc];
            }
#pragma unroll
            for (int mf = 0; mf < 4; mf++) {
                int base = (m0 + mf * 16 + g) * rstride + cofs;
                uint32_t a0 = Xw[base + (kb ^ (4 * g))];
                uint32_t a1 = Xw[base + 8 * rstride + (kb ^ (4 * g))];
                uint32_t a2 = Xw[base + ((kb + 4) ^ (4 * g))];
                uint32_t a3 = Xw[base + 8 * rstride + ((kb + 4) ^ (4 * g))];
#pragma unroll
                for (int nf = 0; nf < 8; nf++)
                    MMA_TF32(c[mf][nf], a0, a1, a2, a3, b0r[nf], b1r[nf]);
            }
        }
    };

    // ======== phase 1: T = ea @ We1_e (K=32, W1e @ buf0) ========
    CP_WAIT1();                 // group A arrived (B may pend)
    __syncthreads();
    compute((const uint32_t*)sm, 32, 0, (const uint32_t*)(sm + 131072));
    __syncthreads();            // Xe region + buf0 free

    // group C: W2 chunk1 -> buf0 (overlaps epilogue + P-merge)
    issue_w(g_W2r, 1, 0);
    CP_COMMIT();

    // epilogue A: write raw T into Ys (swizzled), zero accumulators
#pragma unroll
    for (int mf = 0; mf < 4; mf++) {
        int r0r = m0 + mf * 16 + g;
#pragma unroll
        for (int nf = 0; nf < 8; nf++) {
            int cc = n0 + 8 * nf + 2 * t4;
            int w = (cc & ~31) + ((cc & 31) ^ (4 * g));
            *(float2*)&Ys[r0r * 128 + w]       = make_float2(c[mf][nf][0], c[mf][nf][1]);
            *(float2*)&Ys[(r0r + 8) * 128 + w] = make_float2(c[mf][nf][2], c[mf][nf][3]);
#pragma unroll
            for (int j = 0; j < 4; j++) c[mf][nf][j] = 0.0f;
        }
    }
    __syncthreads();            // fragment-map writes -> row-map reads

    // P-merge: Y = relu(T + P[src].lo + P[dst].hi + b1)   (row-major float4)
#pragma unroll 4
    for (int i = 0; i < 32; i++) {
        int f = tid + i * 256;
        int row = f >> 5, c4 = f & 31;
        int w = row * 128 + (c4 >> 3) * 32 + ((4 * (c4 & 7)) ^ (4 * (row & 7)));
        float4 t = *(const float4*)&Ys[w];
        float4 ps = *(const float4*)(g_P + (size_t)sSrc[row] * 256 + 4 * c4);
        float4 pd = *(const float4*)(g_P + (size_t)sDst[row] * 256 + 128 + 4 * c4);
        float4 b = *(const float4*)&sb1[4 * c4];
        float4 y;
        y.x = fmaxf(t.x + ps.x + pd.x + b.x, 0.0f);
        y.y = fmaxf(t.y + ps.y + pd.y + b.y, 0.0f);
        y.z = fmaxf(t.z + ps.z + pd.z + b.z, 0.0f);
        y.w = fmaxf(t.w + ps.w + pd.w + b.w, 0.0f);
        *(float4*)&Ys[w] = y;
    }

    // ======== phase 2: K=128, chunks 0..3, buffers 1,0,1,0 ========
    const uint32_t* wb0 = (const uint32_t*)(sm + 131072);
    const uint32_t* wb1 = (const uint32_t*)(sm + 131072) + 4096;
    // ch0 (buf1, group B)
    CP_WAIT1();
    __syncthreads();            // publishes P-merge Ys + B's data
    compute((const uint32_t*)sm, 128, 0, wb1);
    // ch1 (buf0, group C)
    CP_WAIT0();
    __syncthreads();
    issue_w(g_W2r, 2, 1); CP_COMMIT();   // group D -> buf1
    compute((const uint32_t*)sm, 128, 32, wb0);
    // ch2 (buf1, group D)
    CP_WAIT0();
    __syncthreads();
    issue_w(g_W2r, 3, 0); CP_COMMIT();   // group E -> buf0
    compute((const uint32_t*)sm, 128, 64, wb1);
    // ch3 (buf0, group E)
    CP_WAIT0();
    __syncthreads();
    compute((const uint32_t*)sm, 128, 96, wb0);
    __syncthreads();            // all warps done reading Ys

    // stage messages (+bias b2) into Ys
#pragma unroll
    for (int mf = 0; mf < 4; mf++) {
        int r0r = m0 + mf * 16 + g;
#pragma unroll
        for (int nf = 0; nf < 8; nf++) {
            int cc = n0 + 8 * nf + 2 * t4;
            float bb0 = sb2[cc], bb1 = sb2[cc + 1];
            int w = (cc & ~31) + ((cc & 31) ^ (4 * g));
            *(float2*)&Ys[r0r * 128 + w] =
                make_float2(c[mf][nf][0] + bb0, c[mf][nf][1] + bb1);
            *(float2*)&Ys[(r0r + 8) * 128 + w] =
                make_float2(c[mf][nf][2] + bb0, c[mf][nf][3] + bb1);
        }
    }
    __syncthreads();

    // coalesced vectorized scatter-add (one dst row per warp-instr)
#pragma unroll 4
    for (int i = 0; i < 32; i++) {
        int f = tid + i * 256;
        int row = f >> 5, c4 = f & 31;
        int w = row * 128 + (c4 >> 3) * 32 + ((4 * (c4 & 7)) ^ (4 * (row & 7)));
        float4 v = *(const float4*)&Ys[w];
        float* gp = g_mi + (size_t)sDst[row] * HID + 4 * c4;
        asm volatile("red.global.add.v4.f32 [%0], {%1,%2,%3,%4};"
                     :: "l"(gp), "f"(v.x), "f"(v.y), "f"(v.z), "f"(v.w) : "memory");
    }
}

// =================================================================
// Node MLP via 3xTF32 split mma — lean schedule (unchanged from R11)
// =================================================================
#define NODE_SMEM 99328

__global__ __launch_bounds__(256, 2) void node_kernel_m(
    const float* __restrict__ h,
    const float* __restrict__ b1g, const float* __restrict__ b2g,
    float* __restrict__ out)
{
    extern __shared__ char sm[];
    const uint32_t smb = smem_u32(sm);
    float* Ys  = (float*)sm;
    float* sb1 = (float*)(sm + 98304);
    float* sb2 = (float*)(sm + 98816);

    const int tid  = threadIdx.x;
    const int lane = tid & 31, wid = tid >> 5;
    const int g    = lane >> 2, t4 = lane & 3;
    const int m0   = (wid >> 1) * 16;
    const int n0   = (wid & 1) * 64;
    const int r0   = blockIdx.x * 64;

    if (tid < 128) { sb1[tid] = b1g[tid]; sb2[tid] = b2g[tid]; }

    auto issue_x = [&](int ch, int b) {
        uint32_t xb = smb + b * 8192;
#pragma unroll
        for (int i = 0; i < 2; i++) {
            int f = tid + i * 256;
            int row = f >> 3, q = f & 7;
            int gr = r0 + row; if (gr >= N_NODES) gr = 0;
            const float* gp = (ch < 4)
                ? h    + (size_t)gr * DNODE + ch * 32 + q * 4
                : g_mi + (size_t)gr * HID   + (ch - 4) * 32 + q * 4;
            uint32_t ds = xb + 4u * (uint32_t)(row * 32 + ((4 * q) ^ (4 * (row & 7))));
            CP_ASYNC(ds, gp);
        }
    };
    auto issue_w = [&](const float* Whi, const float* Wlo, int ch, int b) {
        uint32_t base_hi = smb + 32768 + b * 32768;
#pragma unroll
        for (int i = 0; i < 4; i++) {
            int f = tid + i * 256;
            int k = f >> 5, n4 = f & 31;
            uint32_t off = 4u * (uint32_t)(k * 128 + ((4 * n4) ^ (8 * (k & 3))));
            CP_ASYNC(base_hi + off,         Whi + (size_t)(ch * 32 + k) * 128 + n4 * 4);
            CP_ASYNC(base_hi + 16384 + off, Wlo + (size_t)(ch * 32 + k) * 128 + n4 * 4);
        }
    };

    float c[8][4];
#pragma unroll
    for (int nf = 0; nf < 8; nf++)
#pragma unroll
        for (int j = 0; j < 4; j++) c[nf][j] = 0.0f;

    auto computeN = [&](const uint32_t* Xw, int rstride, int cofs,
                        const uint32_t* Whi, const uint32_t* Wlo) {
#pragma unroll
        for (int s = 0; s < 4; s++) {
            const int kb = 8 * s + t4;
            int base0 = (m0 + g) * rstride + cofs;
            int base1 = (m0 + 8 + g) * rstride + cofs;
            float x0 = __uint_as_float(Xw[base0 + (kb ^ (4 * g))]);
            float x1 = __uint_as_float(Xw[base1 + (kb ^ (4 * g))]);
            float x2 = __uint_as_float(Xw[base0 + ((kb + 4) ^ (4 * g))]);
            float x3 = __uint_as_float(Xw[base1 + ((kb + 4) ^ (4 * g))]);
            uint32_t h0 = rna(x0), h1 = rna(x1), h2 = rna(x2), h3 = rna(x3);
            uint32_t l0 = rna(x0 - __uint_as_float(h0));
            uint32_t l1 = rna(x1 - __uint_as_float(h1));
            uint32_t l2 = rna(x2 - __uint_as_float(h2));
            uint32_t l3 = rna(x3 - __uint_as_float(h3));
#pragma unroll
            for (int nf = 0; nf < 8; nf++) {
                int wc = (n0 + 8 * nf + g) ^ (8 * t4);
                uint32_t bh0 = Whi[kb * 128 + wc], bh1 = Whi[(kb + 4) * 128 + wc];
                uint32_t bl0 = Wlo[kb * 128 + wc], bl1 = Wlo[(kb + 4) * 128 + wc];
                MMA_TF32(c[nf], h0, h1, h2, h3, bh0, bh1);
                MMA_TF32(c[nf], l0, l1, l2, l3, bh0, bh1);
                MMA_TF32(c[nf], h0, h1, h2, h3, bl0, bl1);
            }
        }
    };

    // ======== layer 1: K=256, 8 chunks — one sync per chunk ========
    issue_x(0, 0); issue_w(g_Wh1hi, g_Wh1lo, 0, 0); CP_COMMIT();
    for (int ch = 0; ch < 8; ch++) {
        CP_WAIT0();
        __syncthreads();
        if (ch < 7) {
            issue_x(ch + 1, (ch + 1) & 1);
            issue_w(g_Wh1hi, g_Wh1lo, ch + 1, (ch + 1) & 1);
            CP_COMMIT();
        }
        computeN((const uint32_t*)sm + (ch & 1) * 2048, 32, 0,
                 (const uint32_t*)(sm + 32768 + (ch & 1) * 32768),
                 (const uint32_t*)(sm + 32768 + (ch & 1) * 32768 + 16384));
    }
    __syncthreads();   // last compute done before Ys (overlaps X bufs) is written

    // ---- epilogue 1: relu(x + b1) -> Ys (swizzled), zero c ----
#pragma unroll
    for (int nf = 0; nf < 8; nf++) {
        int cc = n0 + 8 * nf + 2 * t4;
        float bb0 = sb1[cc], bb1 = sb1[cc + 1];
        int w = (cc & ~31) + ((cc & 31) ^ (4 * g));
        *(float2*)&Ys[(m0 + g) * 128 + w] =
            make_float2(fmaxf(c[nf][0] + bb0, 0.0f), fmaxf(c[nf][1] + bb1, 0.0f));
        *(float2*)&Ys[(m0 + 8 + g) * 128 + w] =
            make_float2(fmaxf(c[nf][2] + bb0, 0.0f), fmaxf(c[nf][3] + bb1, 0.0f));
#pragma unroll
        for (int j = 0; j < 4; j++) c[nf][j] = 0.0f;
    }
    issue_w(g_Wh2hi, g_Wh2lo, 0, 0); CP_COMMIT();

    // ======== layer 2: K=128, 4 chunks — one sync per chunk ========
    for (int ch = 0; ch < 4; ch++) {
        CP_WAIT0();
        __syncthreads();   // ch0's sync also publishes epilogue Ys writes
        if (ch < 3) {
            issue_w(g_Wh2hi, g_Wh2lo, ch + 1, (ch + 1) & 1);
            CP_COMMIT();
        }
        computeN((const uint32_t*)sm, 128, ch * 32,
                 (const uint32_t*)(sm + 32768 + (ch & 1) * 32768),
                 (const uint32_t*)(sm + 32768 + (ch & 1) * 32768 + 16384));
    }

    // ---- store out = c + b2 (own accumulators only) ----
#pragma unroll
    for (int nf = 0; nf < 8; nf++) {
        int cc = n0 + 8 * nf + 2 * t4;
        float bb0 = sb2[cc], bb1 = sb2[cc + 1];
        int ra = r0 + m0 + g, rb = ra + 8;
        if (ra < N_NODES)
            *(float2*)(out + (size_t)ra * 128 + cc) =
                make_float2(c[nf][0] + bb0, c[nf][1] + bb1);
        if (rb < N_NODES)
            *(float2*)(out + (size_t)rb * 128 + cc) =
                make_float2(c[nf][2] + bb0, c[nf][3] + bb1);
    }
}

// =================================================================
extern "C" void kernel_launch(void* const* d_in, const int* in_sizes, int n_in,
                              void* d_out, int out_size) {
    const float* h   = (const float*)d_in[0];
    const void*  ei  = d_in[1];
    const float* ea  = (const float*)d_in[2];
    const float* We1 = (const float*)d_in[3];
    const float* be1 = (const float*)d_in[4];
    const float* We2 = (const float*)d_in[5];
    const float* be2 = (const float*)d_in[6];
    const float* Wh1 = (const float*)d_in[7];
    const float* bh1 = (const float*)d_in[8];
    const float* Wh2 = (const float*)d_in[9];
    const float* bh2 = (const float*)d_in[10];
    float* out = (float*)d_out;

    cudaFuncSetAttribute(edge_kernel_m, cudaFuncAttributeMaxDynamicSharedMemorySize, EDGE_SMEM);
    cudaFuncSetAttribute(gemm_P, cudaFuncAttributeMaxDynamicSharedMemorySize, GP_SMEM);
    cudaFuncSetAttribute(node_kernel_m, cudaFuncAttributeMaxDynamicSharedMemorySize, NODE_SMEM);

    convert_kernel<<<(N_EDGES + 255) / 256, 256>>>(ei);
    prep_kernel<<<64, 256>>>(We1, We2, Wh1, Wh2);
    gemm_P<<<(N_NODES + 127) / 128, 256, GP_SMEM>>>(h);
    edge_kernel_m<<<N_EDGES / 256, 256, EDGE_SMEM>>>(ea, be1, be2);
    node_kernel_m<<<(N_NODES + 63) / 64, 256, NODE_SMEM>>>(h, bh1, bh2, out);
}

// round 13
// speedup vs baseline: 1.1503x; 1.1503x over previous
#include <cuda_runtime.h>
#include <cstdint>

#define N_NODES 50000
#define N_EDGES 800000
#define DNODE   128
#define DEDGE   32
#define HID     128

typedef unsigned long long u64;

// ---------------- device-global scratch (no allocations allowed) ----------------
__device__ int   g_src[N_EDGES];
__device__ int   g_dst[N_EDGES];
__device__ float g_mi[(size_t)N_NODES * HID];      // 25.6 MB scatter target
__device__ float g_P[(size_t)N_NODES * 256];       // 51.2 MB: [h@W1a | h@W1b]
__device__ float g_W1r[288 * 128];                 // We1, tf32-rounded (RNA), [K][N]
__device__ float g_W2r[128 * 128];                 // We2, tf32-rounded (RNA), [K][N]
__device__ float g_Wh1hi[256 * 128];               // Wh1 split hi/lo (3xTF32)
__device__ float g_Wh1lo[256 * 128];
__device__ float g_Wh2hi[128 * 128];
__device__ float g_Wh2lo[128 * 128];

// ---------------- helpers ----------------
__device__ __forceinline__ uint32_t smem_u32(const void* p) {
    uint32_t a;
    asm("{ .reg .u64 t; cvta.to.shared.u64 t, %1; cvt.u32.u64 %0, t; }" : "=r"(a) : "l"(p));
    return a;
}
__device__ __forceinline__ uint32_t rna(float x) {
    uint32_t r; asm("cvt.rna.tf32.f32 %0, %1;" : "=r"(r) : "f"(x)); return r;
}

#define CP_ASYNC(ds, gp) \
    asm volatile("cp.async.cg.shared.global [%0], [%1], 16;" :: "r"(ds), "l"(gp))
#define CP_COMMIT() asm volatile("cp.async.commit_group;" ::: "memory")
#define CP_WAIT1()  asm volatile("cp.async.wait_group 1;" ::: "memory")
#define CP_WAIT0()  asm volatile("cp.async.wait_group 0;" ::: "memory")

#define MMA_TF32(C, a0, a1, a2, a3, b0, b1) \
    asm volatile("mma.sync.aligned.m16n8k8.row.col.f32.tf32.tf32.f32 " \
        "{%0,%1,%2,%3}, {%4,%5,%6,%7}, {%8,%9}, {%0,%1,%2,%3};" \
        : "+f"((C)[0]), "+f"((C)[1]), "+f"((C)[2]), "+f"((C)[3]) \
        : "r"(a0), "r"(a1), "r"(a2), "r"(a3), "r"(b0), "r"(b1))

// ---------------- aux kernel: dtype-detect + index convert + zero g_mi ----------------
__global__ void convert_kernel(const void* __restrict__ ei) {
    __shared__ int s64;
    if (threadIdx.x == 0) {
        const int* p = (const int*)ei;
        int all0 = 1;
        for (int s = 0; s < 256; s++)
            if (p[2 * s + 1] != 0) { all0 = 0; break; }
        s64 = all0;
    }
    __syncthreads();
    int i = blockIdx.x * blockDim.x + threadIdx.x;
    if (i < N_EDGES) {
        if (s64) {
            const long long* p = (const long long*)ei;
            g_src[i] = (int)p[i];
            g_dst[i] = (int)p[N_EDGES + i];
        } else {
            const int* p = (const int*)ei;
            g_src[i] = p[i];
            g_dst[i] = p[N_EDGES + i];
        }
    }
    size_t n4 = (size_t)N_NODES * HID / 4;
    float4 z = make_float4(0.f, 0.f, 0.f, 0.f);
    for (size_t j = (size_t)blockIdx.x * blockDim.x + threadIdx.x; j < n4;
         j += (size_t)gridDim.x * blockDim.x)
        ((float4*)g_mi)[j] = z;
}

// ---------------- prep: RNA-round edge weights, split node weights hi/lo ----------------
__global__ void prep_kernel(const float* __restrict__ W1, const float* __restrict__ W2,
                            const float* __restrict__ Wh1, const float* __restrict__ Wh2) {
    int t = blockIdx.x * blockDim.x + threadIdx.x;
    int stride = gridDim.x * blockDim.x;
    for (int i = t; i < 288 * 128; i += stride)
        g_W1r[i] = __uint_as_float(rna(W1[i]));
    for (int i = t; i < 128 * 128; i += stride)
        g_W2r[i] = __uint_as_float(rna(W2[i]));
    for (int i = t; i < 256 * 128; i += stride) {
        float w = Wh1[i];
        uint32_t hi = rna(w);
        g_Wh1hi[i] = __uint_as_float(hi);
        g_Wh1lo[i] = __uint_as_float(rna(w - __uint_as_float(hi)));
    }
    for (int i = t; i < 128 * 128; i += stride) {
        float w = Wh2[i];
        uint32_t hi = rna(w);
        g_Wh2hi[i] = __uint_as_float(hi);
        g_Wh2lo[i] = __uint_as_float(rna(w - __uint_as_float(hi)));
    }
}

// =================================================================
// Precompute P = h @ [We1_a | We1_b]  (50k x 128 x 256, tf32 mma)
// =================================================================
#define GP_SMEM 98304

__global__ __launch_bounds__(256) void gemm_P(const float* __restrict__ h) {
    extern __shared__ char sm[];
    const uint32_t smb = smem_u32(sm);
    const int tid = threadIdx.x, lane = tid & 31, wid = tid >> 5;
    const int g = lane >> 2, t4 = lane & 3;
    const int m0 = (wid >> 2) * 64, n0 = (wid & 3) * 64;
    const int r0 = blockIdx.x * 128;

    auto issue_x = [&](int ch, int b) {
        uint32_t xb = smb + b * 16384;
#pragma unroll
        for (int i = 0; i < 4; i++) {
            int f = tid + i * 256;
            int row = f >> 3, q = f & 7;
            int gr = r0 + row; if (gr >= N_NODES) gr = 0;
            const float* gp = h + (size_t)gr * DNODE + ch * 32 + q * 4;
            uint32_t ds = xb + 4u * (uint32_t)(row * 32 + ((4 * q) ^ (4 * (row & 7))));
            CP_ASYNC(ds, gp);
        }
    };
    auto issue_w = [&](int ch, int b) {
        uint32_t wb = smb + 32768 + b * 32768;
#pragma unroll
        for (int i = 0; i < 8; i++) {
            int f = tid + i * 256;
            int k = f >> 6, n4 = f & 63;
            int n = 4 * n4;
            const float* gp = (n < 128)
                ? g_W1r + (size_t)(ch * 32 + k) * 128 + n
                : g_W1r + (size_t)(128 + ch * 32 + k) * 128 + (n - 128);
            uint32_t ds = wb + 4u * (uint32_t)(k * 256 + (n ^ (8 * (k & 3))));
            CP_ASYNC(ds, gp);
        }
    };

    float c[4][8][4];
#pragma unroll
    for (int mf = 0; mf < 4; mf++)
#pragma unroll
        for (int nf = 0; nf < 8; nf++)
#pragma unroll
            for (int j = 0; j < 4; j++) c[mf][nf][j] = 0.0f;

    issue_x(0, 0); issue_w(0, 0); CP_COMMIT();
    for (int ch = 0; ch < 4; ch++) {
        CP_WAIT0();
        __syncthreads();
        if (ch < 3) {
            issue_x(ch + 1, (ch + 1) & 1);
            issue_w(ch + 1, (ch + 1) & 1);
            CP_COMMIT();
        }
        const uint32_t* Xw = (const uint32_t*)sm + (ch & 1) * 4096;
        const uint32_t* Ww = (const uint32_t*)(sm + 32768) + (ch & 1) * 8192;
#pragma unroll
        for (int s = 0; s < 4; s++) {
            const int kb = 8 * s + t4;
            uint32_t b0r[8], b1r[8];
#pragma unroll
            for (int nf = 0; nf < 8; nf++) {
                int wc = (n0 + 8 * nf + g) ^ (8 * t4);
                b0r[nf] = Ww[kb * 256 + wc];
                b1r[nf] = Ww[(kb + 4) * 256 + wc];
            }
#pragma unroll
            for (int mf = 0; mf < 4; mf++) {
                int base = (m0 + mf * 16 + g) * 32;
                uint32_t a0 = Xw[base + (kb ^ (4 * g))];
                uint32_t a1 = Xw[base + 8 * 32 + (kb ^ (4 * g))];
                uint32_t a2 = Xw[base + ((kb + 4) ^ (4 * g))];
                uint32_t a3 = Xw[base + 8 * 32 + ((kb + 4) ^ (4 * g))];
#pragma unroll
                for (int nf = 0; nf < 8; nf++)
                    MMA_TF32(c[mf][nf], a0, a1, a2, a3, b0r[nf], b1r[nf]);
            }
        }
    }

#pragma unroll
    for (int mf = 0; mf < 4; mf++) {
        int r = m0 + mf * 16 + g;
#pragma unroll
        for (int nf = 0; nf < 8; nf++) {
            int col = n0 + 8 * nf + 2 * t4;
            if (r0 + r < N_NODES)
                *(float2*)(g_P + (size_t)(r0 + r) * 256 + col) =
                    make_float2(c[mf][nf][0], c[mf][nf][1]);
            if (r0 + r + 8 < N_NODES)
                *(float2*)(g_P + (size_t)(r0 + r + 8) * 256 + col) =
                    make_float2(c[mf][nf][2], c[mf][nf][3]);
        }
    }
}

// =================================================================
// Edge kernel v9: R11 data movement + schedule, 512 threads/block.
// 128 edges/block, warp grid 4m x 4n, warp tile 32x32, 2 CTAs/SM
// => 32 warps/SM (double R11's latency-hiding pool, same traffic).
// smem: Ys 64KB @0 (ea X-chunk overlays [0,16384)), W 2x16KB @65536,
//       sb1@98304, sb2@98816, sSrc@99328, sDst@99840
// =================================================================
#define EDGE_SMEM 100352

__global__ __launch_bounds__(512, 2) void edge_kernel_m(
    const float* __restrict__ ea,
    const float* __restrict__ b1g, const float* __restrict__ b2g)
{
    extern __shared__ char sm[];
    const uint32_t smb = smem_u32(sm);
    float* Ys  = (float*)sm;
    float* sb1 = (float*)(sm + 98304);
    float* sb2 = (float*)(sm + 98816);
    int*   sSrc = (int*)(sm + 99328);
    int*   sDst = (int*)(sm + 99840);

    const int tid  = threadIdx.x;
    const int lane = tid & 31, wid = tid >> 5;
    const int g    = lane >> 2, t4 = lane & 3;
    const int m0   = (wid >> 2) * 32;     // 4 m-warps x 32 rows
    const int n0   = (wid & 3) * 32;      // 4 n-warps x 32 cols
    const int e0   = blockIdx.x * 128;

    if (tid < 128) {
        sb1[tid] = b1g[tid];
        sb2[tid] = b2g[tid];
        sSrc[tid] = g_src[e0 + tid];
        sDst[tid] = g_dst[e0 + tid];
    }

    auto issue_w = [&](const float* W, int ch, int wb) {
        uint32_t wbase = smb + 65536 + wb * 16384;
#pragma unroll
        for (int i = 0; i < 2; i++) {
            int f = tid + i * 512;
            int k = f >> 5, n4 = f & 31;
            const float* gp = W + (size_t)(ch * 32 + k) * 128 + n4 * 4;
            uint32_t ds = wbase + 4u * (uint32_t)(k * 128 + ((4 * n4) ^ (8 * (k & 3))));
            CP_ASYNC(ds, gp);
        }
    };

    // group A: ea chunk (128 rows x 32 floats) + W1e (buf0)
#pragma unroll
    for (int i = 0; i < 2; i++) {
        int f = tid + i * 512;
        int row = f >> 3, q = f & 7;
        const float* gp = ea + (size_t)(e0 + row) * DEDGE + q * 4;
        uint32_t ds = smb + 4u * (uint32_t)(row * 32 + ((4 * q) ^ (4 * (row & 7))));
        CP_ASYNC(ds, gp);
    }
    issue_w(g_W1r, 8, 0);
    CP_COMMIT();
    // group B: W2 chunk0 -> buf1 (prefetched across phase 1 + merge)
    issue_w(g_W2r, 0, 1);
    CP_COMMIT();

    float c[2][4][4];
#pragma unroll
    for (int mf = 0; mf < 2; mf++)
#pragma unroll
        for (int nf = 0; nf < 4; nf++)
#pragma unroll
            for (int j = 0; j < 4; j++) c[mf][nf][j] = 0.0f;

    auto compute = [&](const uint32_t* Xw, int rstride, int cofs, const uint32_t* Ww) {
#pragma unroll
        for (int s = 0; s < 4; s++) {
            const int kb = 8 * s + t4;
            uint32_t b0r[4], b1r[4];
#pragma unroll
            for (int nf = 0; nf < 4; nf++) {
                int wc = (n0 + 8 * nf + g) ^ (8 * t4);
                b0r[nf] = Ww[kb * 128 + wc];
                b1r[nf] = Ww[(kb + 4) * 128 + wc];
            }
#pragma unroll
            for (int mf = 0; mf < 2; mf++) {
                int base = (m0 + mf * 16 + g) * rstride + cofs;
                uint32_t a0 = Xw[base + (kb ^ (4 * g))];
                uint32_t a1 = Xw[base + 8 * rstride + (kb ^ (4 * g))];
                uint32_t a2 = Xw[base + ((kb + 4) ^ (4 * g))];
                uint32_t a3 = Xw[base + 8 * rstride + ((kb + 4) ^ (4 * g))];
#pragma unroll
                for (int nf = 0; nf < 4; nf++)
                    MMA_TF32(c[mf][nf], a0, a1, a2, a3, b0r[nf], b1r[nf]);
            }
        }
    };

    // ======== phase 1: T = ea @ We1_e (K=32, W1e @ buf0) ========
    CP_WAIT1();                 // group A arrived (B may pend)
    __syncthreads();
    compute((const uint32_t*)sm, 32, 0, (const uint32_t*)(sm + 65536));
    __syncthreads();            // Xe region + buf0 free

    // group C: W2 chunk1 -> buf0 (overlaps epilogue + P-merge)
    issue_w(g_W2r, 1, 0);
    CP_COMMIT();

    // epilogue A: write raw T into Ys (swizzled), zero accumulators
#pragma unroll
    for (int mf = 0; mf < 2; mf++) {
        int r0r = m0 + mf * 16 + g;
#pragma unroll
        for (int nf = 0; nf < 4; nf++) {
            int cc = n0 + 8 * nf + 2 * t4;
            int w = (cc & ~31) + ((cc & 31) ^ (4 * g));
            *(float2*)&Ys[r0r * 128 + w]       = make_float2(c[mf][nf][0], c[mf][nf][1]);
            *(float2*)&Ys[(r0r + 8) * 128 + w] = make_float2(c[mf][nf][2], c[mf][nf][3]);
#pragma unroll
            for (int j = 0; j < 4; j++) c[mf][nf][j] = 0.0f;
        }
    }
    __syncthreads();            // fragment-map writes -> row-map reads

    // P-merge: Y = relu(T + P[src].lo + P[dst].hi + b1)   (row-major float4)
#pragma unroll 4
    for (int i = 0; i < 8; i++) {
        int f = tid + i * 512;
        int row = f >> 5, c4 = f & 31;
        int w = row * 128 + (c4 >> 3) * 32 + ((4 * (c4 & 7)) ^ (4 * (row & 7)));
        float4 t = *(const float4*)&Ys[w];
        float4 ps = *(const float4*)(g_P + (size_t)sSrc[row] * 256 + 4 * c4);
        float4 pd = *(const float4*)(g_P + (size_t)sDst[row] * 256 + 128 + 4 * c4);
        float4 b = *(const float4*)&sb1[4 * c4];
        float4 y;
        y.x = fmaxf(t.x + ps.x + pd.x + b.x, 0.0f);
        y.y = fmaxf(t.y + ps.y + pd.y + b.y, 0.0f);
        y.z = fmaxf(t.z + ps.z + pd.z + b.z, 0.0f);
        y.w = fmaxf(t.w + ps.w + pd.w + b.w, 0.0f);
        *(float4*)&Ys[w] = y;
    }

    // ======== phase 2: K=128, chunks 0..3, buffers 1,0,1,0 ========
    const uint32_t* wb0 = (const uint32_t*)(sm + 65536);
    const uint32_t* wb1 = (const uint32_t*)(sm + 65536) + 4096;
    // ch0 (buf1, group B)
    CP_WAIT1();
    __syncthreads();            // publishes P-merge Ys + B's data
    compute((const uint32_t*)sm, 128, 0, wb1);
    // ch1 (buf0, group C)
    CP_WAIT0();
    __syncthreads();
    issue_w(g_W2r, 2, 1); CP_COMMIT();   // group D -> buf1
    compute((const uint32_t*)sm, 128, 32, wb0);
    // ch2 (buf1, group D)
    CP_WAIT0();
    __syncthreads();
    issue_w(g_W2r, 3, 0); CP_COMMIT();   // group E -> buf0
    compute((const uint32_t*)sm, 128, 64, wb1);
    // ch3 (buf0, group E)
    CP_WAIT0();
    __syncthreads();
    compute((const uint32_t*)sm, 128, 96, wb0);
    __syncthreads();            // all warps done reading Ys

    // stage messages (+bias b2) into Ys
#pragma unroll
    for (int mf = 0; mf < 2; mf++) {
        int r0r = m0 + mf * 16 + g;
#pragma unroll
        for (int nf = 0; nf < 4; nf++) {
            int cc = n0 + 8 * nf + 2 * t4;
            float bb0 = sb2[cc], bb1 = sb2[cc + 1];
            int w = (cc & ~31) + ((cc & 31) ^ (4 * g));
            *(float2*)&Ys[r0r * 128 + w] =
                make_float2(c[mf][nf][0] + bb0, c[mf][nf][1] + bb1);
            *(float2*)&Ys[(r0r + 8) * 128 + w] =
                make_float2(c[mf][nf][2] + bb0, c[mf][nf][3] + bb1);
        }
    }
    __syncthreads();

    // coalesced vectorized scatter-add (one dst row per warp-instr)
#pragma unroll 4
    for (int i = 0; i < 8; i++) {
        int f = tid + i * 512;
        int row = f >> 5, c4 = f & 31;
        int w = row * 128 + (c4 >> 3) * 32 + ((4 * (c4 & 7)) ^ (4 * (row & 7)));
        float4 v = *(const float4*)&Ys[w];
        float* gp = g_mi + (size_t)sDst[row] * HID + 4 * c4;
        asm volatile("red.global.add.v4.f32 [%0], {%1,%2,%3,%4};"
                     :: "l"(gp), "f"(v.x), "f"(v.y), "f"(v.z), "f"(v.w) : "memory");
    }
}

// =================================================================
// Node MLP via 3xTF32 split mma — lean schedule (unchanged from R11)
// =================================================================
#define NODE_SMEM 99328

__global__ __launch_bounds__(256, 2) void node_kernel_m(
    const float* __restrict__ h,
    const float* __restrict__ b1g, const float* __restrict__ b2g,
    float* __restrict__ out)
{
    extern __shared__ char sm[];
    const uint32_t smb = smem_u32(sm);
    float* Ys  = (float*)sm;
    float* sb1 = (float*)(sm + 98304);
    float* sb2 = (float*)(sm + 98816);

    const int tid  = threadIdx.x;
    const int lane = tid & 31, wid = tid >> 5;
    const int g    = lane >> 2, t4 = lane & 3;
    const int m0   = (wid >> 1) * 16;
    const int n0   = (wid & 1) * 64;
    const int r0   = blockIdx.x * 64;

    if (tid < 128) { sb1[tid] = b1g[tid]; sb2[tid] = b2g[tid]; }

    auto issue_x = [&](int ch, int b) {
        uint32_t xb = smb + b * 8192;
#pragma unroll
        for (int i = 0; i < 2; i++) {
            int f = tid + i * 256;
            int row = f >> 3, q = f & 7;
            int gr = r0 + row; if (gr >= N_NODES) gr = 0;
            const float* gp = (ch < 4)
                ? h    + (size_t)gr * DNODE + ch * 32 + q * 4
                : g_mi + (size_t)gr * HID   + (ch - 4) * 32 + q * 4;
            uint32_t ds = xb + 4u * (uint32_t)(row * 32 + ((4 * q) ^ (4 * (row & 7))));
            CP_ASYNC(ds, gp);
        }
    };
    auto issue_w = [&](const float* Whi, const float* Wlo, int ch, int b) {
        uint32_t base_hi = smb + 32768 + b * 32768;
#pragma unroll
        for (int i = 0; i < 4; i++) {
            int f = tid + i * 256;
            int k = f >> 5, n4 = f & 31;
            uint32_t off = 4u * (uint32_t)(k * 128 + ((4 * n4) ^ (8 * (k & 3))));
            CP_ASYNC(base_hi + off,         Whi + (size_t)(ch * 32 + k) * 128 + n4 * 4);
            CP_ASYNC(base_hi + 16384 + off, Wlo + (size_t)(ch * 32 + k) * 128 + n4 * 4);
        }
    };

    float c[8][4];
#pragma unroll
    for (int nf = 0; nf < 8; nf++)
#pragma unroll
        for (int j = 0; j < 4; j++) c[nf][j] = 0.0f;

    auto computeN = [&](const uint32_t* Xw, int rstride, int cofs,
                        const uint32_t* Whi, const uint32_t* Wlo) {
#pragma unroll
        for (int s = 0; s < 4; s++) {
            const int kb = 8 * s + t4;
            int base0 = (m0 + g) * rstride + cofs;
            int base1 = (m0 + 8 + g) * rstride + cofs;
            float x0 = __uint_as_float(Xw[base0 + (kb ^ (4 * g))]);
            float x1 = __uint_as_float(Xw[base1 + (kb ^ (4 * g))]);
            float x2 = __uint_as_float(Xw[base0 + ((kb + 4) ^ (4 * g))]);
            float x3 = __uint_as_float(Xw[base1 + ((kb + 4) ^ (4 * g))]);
            uint32_t h0 = rna(x0), h1 = rna(x1), h2 = rna(x2), h3 = rna(x3);
            uint32_t l0 = rna(x0 - __uint_as_float(h0));
            uint32_t l1 = rna(x1 - __uint_as_float(h1));
            uint32_t l2 = rna(x2 - __uint_as_float(h2));
            uint32_t l3 = rna(x3 - __uint_as_float(h3));
#pragma unroll
            for (int nf = 0; nf < 8; nf++) {
                int wc = (n0 + 8 * nf + g) ^ (8 * t4);
                uint32_t bh0 = Whi[kb * 128 + wc], bh1 = Whi[(kb + 4) * 128 + wc];
                uint32_t bl0 = Wlo[kb * 128 + wc], bl1 = Wlo[(kb + 4) * 128 + wc];
                MMA_TF32(c[nf], h0, h1, h2, h3, bh0, bh1);
                MMA_TF32(c[nf], l0, l1, l2, l3, bh0, bh1);
                MMA_TF32(c[nf], h0, h1, h2, h3, bl0, bl1);
            }
        }
    };

    // ======== layer 1: K=256, 8 chunks — one sync per chunk ========
    issue_x(0, 0); issue_w(g_Wh1hi, g_Wh1lo, 0, 0); CP_COMMIT();
    for (int ch = 0; ch < 8; ch++) {
        CP_WAIT0();
        __syncthreads();
        if (ch < 7) {
            issue_x(ch + 1, (ch + 1) & 1);
            issue_w(g_Wh1hi, g_Wh1lo, ch + 1, (ch + 1) & 1);
            CP_COMMIT();
        }
        computeN((const uint32_t*)sm + (ch & 1) * 2048, 32, 0,
                 (const uint32_t*)(sm + 32768 + (ch & 1) * 32768),
                 (const uint32_t*)(sm + 32768 + (ch & 1) * 32768 + 16384));
    }
    __syncthreads();   // last compute done before Ys (overlaps X bufs) is written

    // ---- epilogue 1: relu(x + b1) -> Ys (swizzled), zero c ----
#pragma unroll
    for (int nf = 0; nf < 8; nf++) {
        int cc = n0 + 8 * nf + 2 * t4;
        float bb0 = sb1[cc], bb1 = sb1[cc + 1];
        int w = (cc & ~31) + ((cc & 31) ^ (4 * g));
        *(float2*)&Ys[(m0 + g) * 128 + w] =
            make_float2(fmaxf(c[nf][0] + bb0, 0.0f), fmaxf(c[nf][1] + bb1, 0.0f));
        *(float2*)&Ys[(m0 + 8 + g) * 128 + w] =
            make_float2(fmaxf(c[nf][2] + bb0, 0.0f), fmaxf(c[nf][3] + bb1, 0.0f));
#pragma unroll
        for (int j = 0; j < 4; j++) c[nf][j] = 0.0f;
    }
    issue_w(g_Wh2hi, g_Wh2lo, 0, 0); CP_COMMIT();

    // ======== layer 2: K=128, 4 chunks — one sync per chunk ========
    for (int ch = 0; ch < 4; ch++) {
        CP_WAIT0();
        __syncthreads();   // ch0's sync also publishes epilogue Ys writes
        if (ch < 3) {
            issue_w(g_Wh2hi, g_Wh2lo, ch + 1, (ch + 1) & 1);
            CP_COMMIT();
        }
        computeN((const uint32_t*)sm, 128, ch * 32,
                 (const uint32_t*)(sm + 32768 + (ch & 1) * 32768),
                 (const uint32_t*)(sm + 32768 + (ch & 1) * 32768 + 16384));
    }

    // ---- store out = c + b2 (own accumulators only) ----
#pragma unroll
    for (int nf = 0; nf < 8; nf++) {
        int cc = n0 + 8 * nf + 2 * t4;
        float bb0 = sb2[cc], bb1 = sb2[cc + 1];
        int ra = r0 + m0 + g, rb = ra + 8;
        if (ra < N_NODES)
            *(float2*)(out + (size_t)ra * 128 + cc) =
                make_float2(c[nf][0] + bb0, c[nf][1] + bb1);
        if (rb < N_NODES)
            *(float2*)(out + (size_t)rb * 128 + cc) =
                make_float2(c[nf][2] + bb0, c[nf][3] + bb1);
    }
}

// =================================================================
extern "C" void kernel_launch(void* const* d_in, const int* in_sizes, int n_in,
                              void* d_out, int out_size) {
    const float* h   = (const float*)d_in[0];
    const void*  ei  = d_in[1];
    const float* ea  = (const float*)d_in[2];
    const float* We1 = (const float*)d_in[3];
    const float* be1 = (const float*)d_in[4];
    const float* We2 = (const float*)d_in[5];
    const float* be2 = (const float*)d_in[6];
    const float* Wh1 = (const float*)d_in[7];
    const float* bh1 = (const float*)d_in[8];
    const float* Wh2 = (const float*)d_in[9];
    const float* bh2 = (const float*)d_in[10];
    float* out = (float*)d_out;

    cudaFuncSetAttribute(edge_kernel_m, cudaFuncAttributeMaxDynamicSharedMemorySize, EDGE_SMEM);
    cudaFuncSetAttribute(gemm_P, cudaFuncAttributeMaxDynamicSharedMemorySize, GP_SMEM);
    cudaFuncSetAttribute(node_kernel_m, cudaFuncAttributeMaxDynamicSharedMemorySize, NODE_SMEM);

    convert_kernel<<<(N_EDGES + 255) / 256, 256>>>(ei);
    prep_kernel<<<64, 256>>>(We1, We2, Wh1, Wh2);
    gemm_P<<<(N_NODES + 127) / 128, 256, GP_SMEM>>>(h);
    edge_kernel_m<<<N_EDGES / 128, 512, EDGE_SMEM>>>(ea, be1, be2);
    node_kernel_m<<<(N_NODES + 63) / 64, 256, NODE_SMEM>>>(h, bh1, bh2, out);
}

// round 14
// speedup vs baseline: 1.2223x; 1.0626x over previous
#include <cuda_runtime.h>
#include <cstdint>

#define N_NODES 50000
#define N_EDGES 800000
#define DNODE   128
#define DEDGE   32
#define HID     128

typedef unsigned long long u64;

// ---------------- device-global scratch (no allocations allowed) ----------------
__device__ int   g_src[N_EDGES];
__device__ int   g_dst[N_EDGES];
__device__ float g_mi[(size_t)N_NODES * HID];      // 25.6 MB scatter target
__device__ float g_P[(size_t)N_NODES * 256];       // 51.2 MB: [h@W1a | h@W1b]
__device__ float g_W1r[288 * 128];                 // We1, tf32-rounded (RNA), [K][N]
__device__ float g_W2r[128 * 128];                 // We2, tf32-rounded (RNA), [K][N]
__device__ float g_Wh1hi[256 * 128];               // Wh1 split hi/lo (3xTF32)
__device__ float g_Wh1lo[256 * 128];
__device__ float g_Wh2hi[128 * 128];
__device__ float g_Wh2lo[128 * 128];

// ---------------- helpers ----------------
__device__ __forceinline__ uint32_t smem_u32(const void* p) {
    uint32_t a;
    asm("{ .reg .u64 t; cvta.to.shared.u64 t, %1; cvt.u32.u64 %0, t; }" : "=r"(a) : "l"(p));
    return a;
}
__device__ __forceinline__ uint32_t rna(float x) {
    uint32_t r; asm("cvt.rna.tf32.f32 %0, %1;" : "=r"(r) : "f"(x)); return r;
}

#define CP_ASYNC(ds, gp) \
    asm volatile("cp.async.cg.shared.global [%0], [%1], 16;" :: "r"(ds), "l"(gp))
#define CP_COMMIT() asm volatile("cp.async.commit_group;" ::: "memory")
#define CP_WAIT1()  asm volatile("cp.async.wait_group 1;" ::: "memory")
#define CP_WAIT0()  asm volatile("cp.async.wait_group 0;" ::: "memory")

#define MMA_TF32(C, a0, a1, a2, a3, b0, b1) \
    asm volatile("mma.sync.aligned.m16n8k8.row.col.f32.tf32.tf32.f32 " \
        "{%0,%1,%2,%3}, {%4,%5,%6,%7}, {%8,%9}, {%0,%1,%2,%3};" \
        : "+f"((C)[0]), "+f"((C)[1]), "+f"((C)[2]), "+f"((C)[3]) \
        : "r"(a0), "r"(a1), "r"(a2), "r"(a3), "r"(b0), "r"(b1))

// ---------------- prep: RNA-round edge weights, split node weights hi/lo ----------------
__global__ void prep_kernel(const float* __restrict__ W1, const float* __restrict__ W2,
                            const float* __restrict__ Wh1, const float* __restrict__ Wh2) {
    int t = blockIdx.x * blockDim.x + threadIdx.x;
    int stride = gridDim.x * blockDim.x;
    for (int i = t; i < 288 * 128; i += stride)
        g_W1r[i] = __uint_as_float(rna(W1[i]));
    for (int i = t; i < 128 * 128; i += stride)
        g_W2r[i] = __uint_as_float(rna(W2[i]));
    for (int i = t; i < 256 * 128; i += stride) {
        float w = Wh1[i];
        uint32_t hi = rna(w);
        g_Wh1hi[i] = __uint_as_float(hi);
        g_Wh1lo[i] = __uint_as_float(rna(w - __uint_as_float(hi)));
    }
    for (int i = t; i < 128 * 128; i += stride) {
        float w = Wh2[i];
        uint32_t hi = rna(w);
        g_Wh2hi[i] = __uint_as_float(hi);
        g_Wh2lo[i] = __uint_as_float(rna(w - __uint_as_float(hi)));
    }
}

// =================================================================
// Fused kernel: blocks [0, GP_BLOCKS) run gemm_P (P = h @ [We1_a|We1_b]);
// blocks [GP_BLOCKS, GP_BLOCKS+CV_BLOCKS) run convert (index decode +
// dst split + zero g_mi). Independent data -> run concurrently in one
// launch, removing the serial convert+gemm_P+launch-gap time.
// =================================================================
#define GP_BLOCKS 391                   // ceil(50000/128)
#define CV_BLOCKS 3125                  // ceil(800000/256)
#define GP_SMEM 98304

__global__ __launch_bounds__(256) void fused_aux(
    const float* __restrict__ h, const void* __restrict__ ei)
{
    extern __shared__ char sm[];
    const int tid = threadIdx.x;

    if (blockIdx.x >= GP_BLOCKS) {
        // ---------------- convert part ----------------
        const int cbid = blockIdx.x - GP_BLOCKS;
        int* s64p = (int*)sm;
        if (tid == 0) {
            const int* p = (const int*)ei;
            int all0 = 1;
            for (int s = 0; s < 256; s++)
                if (p[2 * s + 1] != 0) { all0 = 0; break; }
            *s64p = all0;
        }
        __syncthreads();
        const int s64 = *s64p;
        int i = cbid * 256 + tid;
        if (i < N_EDGES) {
            if (s64) {
                const long long* p = (const long long*)ei;
                g_src[i] = (int)p[i];
                g_dst[i] = (int)p[N_EDGES + i];
            } else {
                const int* p = (const int*)ei;
                g_src[i] = p[i];
                g_dst[i] = p[N_EDGES + i];
            }
        }
        size_t n4 = (size_t)N_NODES * HID / 4;
        float4 z = make_float4(0.f, 0.f, 0.f, 0.f);
        for (size_t j = (size_t)cbid * 256 + tid; j < n4;
             j += (size_t)CV_BLOCKS * 256)
            ((float4*)g_mi)[j] = z;
        return;
    }

    // ---------------- gemm_P part (verbatim R11 body) ----------------
    const uint32_t smb = smem_u32(sm);
    const int lane = tid & 31, wid = tid >> 5;
    const int g = lane >> 2, t4 = lane & 3;
    const int m0 = (wid >> 2) * 64, n0 = (wid & 3) * 64;
    const int r0 = blockIdx.x * 128;

    auto issue_x = [&](int ch, int b) {
        uint32_t xb = smb + b * 16384;
#pragma unroll
        for (int i = 0; i < 4; i++) {
            int f = tid + i * 256;
            int row = f >> 3, q = f & 7;
            int gr = r0 + row; if (gr >= N_NODES) gr = 0;
            const float* gp = h + (size_t)gr * DNODE + ch * 32 + q * 4;
            uint32_t ds = xb + 4u * (uint32_t)(row * 32 + ((4 * q) ^ (4 * (row & 7))));
            CP_ASYNC(ds, gp);
        }
    };
    auto issue_w = [&](int ch, int b) {
        uint32_t wb = smb + 32768 + b * 32768;
#pragma unroll
        for (int i = 0; i < 8; i++) {
            int f = tid + i * 256;
            int k = f >> 6, n4 = f & 63;
            int n = 4 * n4;
            const float* gp = (n < 128)
                ? g_W1r + (size_t)(ch * 32 + k) * 128 + n
                : g_W1r + (size_t)(128 + ch * 32 + k) * 128 + (n - 128);
            uint32_t ds = wb + 4u * (uint32_t)(k * 256 + (n ^ (8 * (k & 3))));
            CP_ASYNC(ds, gp);
        }
    };

    float c[4][8][4];
#pragma unroll
    for (int mf = 0; mf < 4; mf++)
#pragma unroll
        for (int nf = 0; nf < 8; nf++)
#pragma unroll
            for (int j = 0; j < 4; j++) c[mf][nf][j] = 0.0f;

    issue_x(0, 0); issue_w(0, 0); CP_COMMIT();
    for (int ch = 0; ch < 4; ch++) {
        CP_WAIT0();
        __syncthreads();
        if (ch < 3) {
            issue_x(ch + 1, (ch + 1) & 1);
            issue_w(ch + 1, (ch + 1) & 1);
            CP_COMMIT();
        }
        const uint32_t* Xw = (const uint32_t*)sm + (ch & 1) * 4096;
        const uint32_t* Ww = (const uint32_t*)(sm + 32768) + (ch & 1) * 8192;
#pragma unroll
        for (int s = 0; s < 4; s++) {
            const int kb = 8 * s + t4;
            uint32_t b0r[8], b1r[8];
#pragma unroll
            for (int nf = 0; nf < 8; nf++) {
                int wc = (n0 + 8 * nf + g) ^ (8 * t4);
                b0r[nf] = Ww[kb * 256 + wc];
                b1r[nf] = Ww[(kb + 4) * 256 + wc];
            }
#pragma unroll
            for (int mf = 0; mf < 4; mf++) {
                int base = (m0 + mf * 16 + g) * 32;
                uint32_t a0 = Xw[base + (kb ^ (4 * g))];
                uint32_t a1 = Xw[base + 8 * 32 + (kb ^ (4 * g))];
                uint32_t a2 = Xw[base + ((kb + 4) ^ (4 * g))];
                uint32_t a3 = Xw[base + 8 * 32 + ((kb + 4) ^ (4 * g))];
#pragma unroll
                for (int nf = 0; nf < 8; nf++)
                    MMA_TF32(c[mf][nf], a0, a1, a2, a3, b0r[nf], b1r[nf]);
            }
        }
    }

#pragma unroll
    for (int mf = 0; mf < 4; mf++) {
        int r = m0 + mf * 16 + g;
#pragma unroll
        for (int nf = 0; nf < 8; nf++) {
            int col = n0 + 8 * nf + 2 * t4;
            if (r0 + r < N_NODES)
                *(float2*)(g_P + (size_t)(r0 + r) * 256 + col) =
                    make_float2(c[mf][nf][0], c[mf][nf][1]);
            if (r0 + r + 8 < N_NODES)
                *(float2*)(g_P + (size_t)(r0 + r + 8) * 256 + col) =
                    make_float2(c[mf][nf][2], c[mf][nf][3]);
        }
    }
}

// =================================================================
// Edge kernel (verbatim R11 — converged optimum):
// 128 edges/block, 256 thr, warp grid 4m x 2n (tile 32x64), 2 CTAs/SM,
// lean WAIT->sync->issue->compute schedule, early W2 prefetch.
// smem: Ys 64KB @0 (ea X-chunk overlays [0,16384)), W 2x16KB @65536,
//       sb1@98304, sb2@98816, sSrc@99328, sDst@99840
// =================================================================
#define EDGE_SMEM 100352

__global__ __launch_bounds__(256, 2) void edge_kernel_m(
    const float* __restrict__ ea,
    const float* __restrict__ b1g, const float* __restrict__ b2g)
{
    extern __shared__ char sm[];
    const uint32_t smb = smem_u32(sm);
    float* Ys  = (float*)sm;
    float* sb1 = (float*)(sm + 98304);
    float* sb2 = (float*)(sm + 98816);
    int*   sSrc = (int*)(sm + 99328);
    int*   sDst = (int*)(sm + 99840);

    const int tid  = threadIdx.x;
    const int lane = tid & 31, wid = tid >> 5;
    const int g    = lane >> 2, t4 = lane & 3;
    const int m0   = (wid >> 1) * 32;
    const int n0   = (wid & 1) * 64;
    const int e0   = blockIdx.x * 128;

    if (tid < 128) {
        sb1[tid] = b1g[tid];
        sb2[tid] = b2g[tid];
        sSrc[tid] = g_src[e0 + tid];
        sDst[tid] = g_dst[e0 + tid];
    }

    auto issue_w = [&](const float* W, int ch, int wb) {
        uint32_t wbase = smb + 65536 + wb * 16384;
#pragma unroll
        for (int i = 0; i < 4; i++) {
            int f = tid + i * 256;
            int k = f >> 5, n4 = f & 31;
            const float* gp = W + (size_t)(ch * 32 + k) * 128 + n4 * 4;
            uint32_t ds = wbase + 4u * (uint32_t)(k * 128 + ((4 * n4) ^ (8 * (k & 3))));
            CP_ASYNC(ds, gp);
        }
    };

    // group A: ea chunk + W1e (buf0)
#pragma unroll
    for (int i = 0; i < 4; i++) {
        int f = tid + i * 256;
        int row = f >> 3, q = f & 7;
        const float* gp = ea + (size_t)(e0 + row) * DEDGE + q * 4;
        uint32_t ds = smb + 4u * (uint32_t)(row * 32 + ((4 * q) ^ (4 * (row & 7))));
        CP_ASYNC(ds, gp);
    }
    issue_w(g_W1r, 8, 0);
    CP_COMMIT();
    // group B: W2 chunk0 (buf1) — prefetched across phase 1 + epilogue
    issue_w(g_W2r, 0, 1);
    CP_COMMIT();

    float c[2][8][4];
#pragma unroll
    for (int mf = 0; mf < 2; mf++)
#pragma unroll
        for (int nf = 0; nf < 8; nf++)
#pragma unroll
            for (int j = 0; j < 4; j++) c[mf][nf][j] = 0.0f;

    auto compute = [&](const uint32_t* Xw, int rstride, int cofs, const uint32_t* Ww) {
#pragma unroll
        for (int s = 0; s < 4; s++) {
            const int kb = 8 * s + t4;
            uint32_t b0r[8], b1r[8];
#pragma unroll
            for (int nf = 0; nf < 8; nf++) {
                int wc = (n0 + 8 * nf + g) ^ (8 * t4);
                b0r[nf] = Ww[kb * 128 + wc];
                b1r[nf] = Ww[(kb + 4) * 128 + wc];
            }
#pragma unroll
            for (int mf = 0; mf < 2; mf++) {
                int base = (m0 + mf * 16 + g) * rstride + cofs;
                uint32_t a0 = Xw[base + (kb ^ (4 * g))];
                uint32_t a1 = Xw[base + 8 * rstride + (kb ^ (4 * g))];
                uint32_t a2 = Xw[base + ((kb + 4) ^ (4 * g))];
                uint32_t a3 = Xw[base + 8 * rstride + ((kb + 4) ^ (4 * g))];
#pragma unroll
                for (int nf = 0; nf < 8; nf++)
                    MMA_TF32(c[mf][nf], a0, a1, a2, a3, b0r[nf], b1r[nf]);
            }
        }
    };

    // ======== phase 1: T = ea @ We1_e (K=32, W1e @ buf0) ========
    CP_WAIT1();                 // group A arrived (B may be in flight)
    __syncthreads();
    compute((const uint32_t*)sm, 32, 0, (const uint32_t*)(sm + 65536));
    __syncthreads();            // Xe + buf0 free

    // group C: W2 chunk1 -> buf0 (overlaps epilogue + P-merge)
    issue_w(g_W2r, 1, 0);
    CP_COMMIT();

    // epilogue A: write raw T into Ys (swizzled), zero accumulators
#pragma unroll
    for (int mf = 0; mf < 2; mf++) {
        int r0r = m0 + mf * 16 + g;
#pragma unroll
        for (int nf = 0; nf < 8; nf++) {
            int cc = n0 + 8 * nf + 2 * t4;
            int w = (cc & ~31) + ((cc & 31) ^ (4 * g));
            *(float2*)&Ys[r0r * 128 + w]       = make_float2(c[mf][nf][0], c[mf][nf][1]);
            *(float2*)&Ys[(r0r + 8) * 128 + w] = make_float2(c[mf][nf][2], c[mf][nf][3]);
#pragma unroll
            for (int j = 0; j < 4; j++) c[mf][nf][j] = 0.0f;
        }
    }
    __syncthreads();            // fragment-map writes -> row-map reads

    // P-merge: Y = relu(T + P[src].lo + P[dst].hi + b1)   (row-major float4)
#pragma unroll 4
    for (int i = 0; i < 16; i++) {
        int f = tid + i * 256;
        int row = f >> 5, c4 = f & 31;
        int w = row * 128 + (c4 >> 3) * 32 + ((4 * (c4 & 7)) ^ (4 * (row & 7)));
        float4 t = *(const float4*)&Ys[w];
        float4 ps = *(const float4*)(g_P + (size_t)sSrc[row] * 256 + 4 * c4);
        float4 pd = *(const float4*)(g_P + (size_t)sDst[row] * 256 + 128 + 4 * c4);
        float4 b = *(const float4*)&sb1[4 * c4];
        float4 y;
        y.x = fmaxf(t.x + ps.x + pd.x + b.x, 0.0f);
        y.y = fmaxf(t.y + ps.y + pd.y + b.y, 0.0f);
        y.z = fmaxf(t.z + ps.z + pd.z + b.z, 0.0f);
        y.w = fmaxf(t.w + ps.w + pd.w + b.w, 0.0f);
        *(float4*)&Ys[w] = y;
    }

    // ======== phase 2: K=128, chunks 0..3, buffers 1,0,1,0 ========
    // ch0 (buf1, group B)
    CP_WAIT1();                 // B arrived (C may pend)
    __syncthreads();            // publishes P-merge Ys + B's data; retires merge reads
    compute((const uint32_t*)sm, 128, 0, (const uint32_t*)(sm + 65536) + 4096);
    // ch1 (buf0, group C)
    CP_WAIT0();
    __syncthreads();
    issue_w(g_W2r, 2, 1); CP_COMMIT();   // group D -> buf1 (freed by sync)
    compute((const uint32_t*)sm, 128, 32, (const uint32_t*)(sm + 65536));
    // ch2 (buf1, group D)
    CP_WAIT0();
    __syncthreads();
    issue_w(g_W2r, 3, 0); CP_COMMIT();   // group E -> buf0
    compute((const uint32_t*)sm, 128, 64, (const uint32_t*)(sm + 65536) + 4096);
    // ch3 (buf0, group E)
    CP_WAIT0();
    __syncthreads();
    compute((const uint32_t*)sm, 128, 96, (const uint32_t*)(sm + 65536));
    __syncthreads();            // all warps done reading Ys

    // stage messages (+bias b2) into Ys
#pragma unroll
    for (int mf = 0; mf < 2; mf++) {
        int r0r = m0 + mf * 16 + g;
#pragma unroll
        for (int nf = 0; nf < 8; nf++) {
            int cc = n0 + 8 * nf + 2 * t4;
            float bb0 = sb2[cc], bb1 = sb2[cc + 1];
            int w = (cc & ~31) + ((cc & 31) ^ (4 * g));
            *(float2*)&Ys[r0r * 128 + w] =
                make_float2(c[mf][nf][0] + bb0, c[mf][nf][1] + bb1);
            *(float2*)&Ys[(r0r + 8) * 128 + w] =
                make_float2(c[mf][nf][2] + bb0, c[mf][nf][3] + bb1);
        }
    }
    __syncthreads();

    // coalesced vectorized scatter-add (one dst row per warp-instr)
#pragma unroll 4
    for (int i = 0; i < 16; i++) {
        int f = tid + i * 256;
        int row = f >> 5, c4 = f & 31;
        int w = row * 128 + (c4 >> 3) * 32 + ((4 * (c4 & 7)) ^ (4 * (row & 7)));
        float4 v = *(const float4*)&Ys[w];
        float* gp = g_mi + (size_t)sDst[row] * HID + 4 * c4;
        asm volatile("red.global.add.v4.f32 [%0], {%1,%2,%3,%4};"
                     :: "l"(gp), "f"(v.x), "f"(v.y), "f"(v.z), "f"(v.w) : "memory");
    }
}

// =================================================================
// Node MLP via 3xTF32 split mma — lean schedule (verbatim R11)
// =================================================================
#define NODE_SMEM 99328

__global__ __launch_bounds__(256, 2) void node_kernel_m(
    const float* __restrict__ h,
    const float* __restrict__ b1g, const float* __restrict__ b2g,
    float* __restrict__ out)
{
    extern __shared__ char sm[];
    const uint32_t smb = smem_u32(sm);
    float* Ys  = (float*)sm;
    float* sb1 = (float*)(sm + 98304);
    float* sb2 = (float*)(sm + 98816);

    const int tid  = threadIdx.x;
    const int lane = tid & 31, wid = tid >> 5;
    const int g    = lane >> 2, t4 = lane & 3;
    const int m0   = (wid >> 1) * 16;
    const int n0   = (wid & 1) * 64;
    const int r0   = blockIdx.x * 64;

    if (tid < 128) { sb1[tid] = b1g[tid]; sb2[tid] = b2g[tid]; }

    auto issue_x = [&](int ch, int b) {
        uint32_t xb = smb + b * 8192;
#pragma unroll
        for (int i = 0; i < 2; i++) {
            int f = tid + i * 256;
            int row = f >> 3, q = f & 7;
            int gr = r0 + row; if (gr >= N_NODES) gr = 0;
            const float* gp = (ch < 4)
                ? h    + (size_t)gr * DNODE + ch * 32 + q * 4
                : g_mi + (size_t)gr * HID   + (ch - 4) * 32 + q * 4;
            uint32_t ds = xb + 4u * (uint32_t)(row * 32 + ((4 * q) ^ (4 * (row & 7))));
            CP_ASYNC(ds, gp);
        }
    };
    auto issue_w = [&](const float* Whi, const float* Wlo, int ch, int b) {
        uint32_t base_hi = smb + 32768 + b * 32768;
#pragma unroll
        for (int i = 0; i < 4; i++) {
            int f = tid + i * 256;
            int k = f >> 5, n4 = f & 31;
            uint32_t off = 4u * (uint32_t)(k * 128 + ((4 * n4) ^ (8 * (k & 3))));
            CP_ASYNC(base_hi + off,         Whi + (size_t)(ch * 32 + k) * 128 + n4 * 4);
            CP_ASYNC(base_hi + 16384 + off, Wlo + (size_t)(ch * 32 + k) * 128 + n4 * 4);
        }
    };

    float c[8][4];
#pragma unroll
    for (int nf = 0; nf < 8; nf++)
#pragma unroll
        for (int j = 0; j < 4; j++) c[nf][j] = 0.0f;

    auto computeN = [&](const uint32_t* Xw, int rstride, int cofs,
                        const uint32_t* Whi, const uint32_t* Wlo) {
#pragma unroll
        for (int s = 0; s < 4; s++) {
            const int kb = 8 * s + t4;
            int base0 = (m0 + g) * rstride + cofs;
            int base1 = (m0 + 8 + g) * rstride + cofs;
            float x0 = __uint_as_float(Xw[base0 + (kb ^ (4 * g))]);
            float x1 = __uint_as_float(Xw[base1 + (kb ^ (4 * g))]);
            float x2 = __uint_as_float(Xw[base0 + ((kb + 4) ^ (4 * g))]);
            float x3 = __uint_as_float(Xw[base1 + ((kb + 4) ^ (4 * g))]);
            uint32_t h0 = rna(x0), h1 = rna(x1), h2 = rna(x2), h3 = rna(x3);
            uint32_t l0 = rna(x0 - __uint_as_float(h0));
            uint32_t l1 = rna(x1 - __uint_as_float(h1));
            uint32_t l2 = rna(x2 - __uint_as_float(h2));
            uint32_t l3 = rna(x3 - __uint_as_float(h3));
#pragma unroll
            for (int nf = 0; nf < 8; nf++) {
                int wc = (n0 + 8 * nf + g) ^ (8 * t4);
                uint32_t bh0 = Whi[kb * 128 + wc], bh1 = Whi[(kb + 4) * 128 + wc];
                uint32_t bl0 = Wlo[kb * 128 + wc], bl1 = Wlo[(kb + 4) * 128 + wc];
                MMA_TF32(c[nf], h0, h1, h2, h3, bh0, bh1);
                MMA_TF32(c[nf], l0, l1, l2, l3, bh0, bh1);
                MMA_TF32(c[nf], h0, h1, h2, h3, bl0, bl1);
            }
        }
    };

    // ======== layer 1: K=256, 8 chunks — one sync per chunk ========
    issue_x(0, 0); issue_w(g_Wh1hi, g_Wh1lo, 0, 0); CP_COMMIT();
    for (int ch = 0; ch < 8; ch++) {
        CP_WAIT0();
        __syncthreads();
        if (ch < 7) {
            issue_x(ch + 1, (ch + 1) & 1);
            issue_w(g_Wh1hi, g_Wh1lo, ch + 1, (ch + 1) & 1);
            CP_COMMIT();
        }
        computeN((const uint32_t*)sm + (ch & 1) * 2048, 32, 0,
                 (const uint32_t*)(sm + 32768 + (ch & 1) * 32768),
                 (const uint32_t*)(sm + 32768 + (ch & 1) * 32768 + 16384));
    }
    __syncthreads();   // last compute done before Ys (overlaps X bufs) is written

    // ---- epilogue 1: relu(x + b1) -> Ys (swizzled), zero c ----
#pragma unroll
    for (int nf = 0; nf < 8; nf++) {
        int cc = n0 + 8 * nf + 2 * t4;
        float bb0 = sb1[cc], bb1 = sb1[cc + 1];
        int w = (cc & ~31) + ((cc & 31) ^ (4 * g));
        *(float2*)&Ys[(m0 + g) * 128 + w] =
            make_float2(fmaxf(c[nf][0] + bb0, 0.0f), fmaxf(c[nf][1] + bb1, 0.0f));
        *(float2*)&Ys[(m0 + 8 + g) * 128 + w] =
            make_float2(fmaxf(c[nf][2] + bb0, 0.0f), fmaxf(c[nf][3] + bb1, 0.0f));
#pragma unroll
        for (int j = 0; j < 4; j++) c[nf][j] = 0.0f;
    }
    issue_w(g_Wh2hi, g_Wh2lo, 0, 0); CP_COMMIT();

    // ======== layer 2: K=128, 4 chunks — one sync per chunk ========
    for (int ch = 0; ch < 4; ch++) {
        CP_WAIT0();
        __syncthreads();   // ch0's sync also publishes epilogue Ys writes
        if (ch < 3) {
            issue_w(g_Wh2hi, g_Wh2lo, ch + 1, (ch + 1) & 1);
            CP_COMMIT();
        }
        computeN((const uint32_t*)sm, 128, ch * 32,
                 (const uint32_t*)(sm + 32768 + (ch & 1) * 32768),
                 (const uint32_t*)(sm + 32768 + (ch & 1) * 32768 + 16384));
    }

    // ---- store out = c + b2 (own accumulators only) ----
#pragma unroll
    for (int nf = 0; nf < 8; nf++) {
        int cc = n0 + 8 * nf + 2 * t4;
        float bb0 = sb2[cc], bb1 = sb2[cc + 1];
        int ra = r0 + m0 + g, rb = ra + 8;
        if (ra < N_NODES)
            *(float2*)(out + (size_t)ra * 128 + cc) =
                make_float2(c[nf][0] + bb0, c[nf][1] + bb1);
        if (rb < N_NODES)
            *(float2*)(out + (size_t)rb * 128 + cc) =
                make_float2(c[nf][2] + bb0, c[nf][3] + bb1);
    }
}

// =================================================================
extern "C" void kernel_launch(void* const* d_in, const int* in_sizes, int n_in,
                              void* d_out, int out_size) {
    const float* h   = (const float*)d_in[0];
    const void*  ei  = d_in[1];
    const float* ea  = (const float*)d_in[2];
    const float* We1 = (const float*)d_in[3];
    const float* be1 = (const float*)d_in[4];
    const float* We2 = (const float*)d_in[5];
    const float* be2 = (const float*)d_in[6];
    const float* Wh1 = (const float*)d_in[7];
    const float* bh1 = (const float*)d_in[8];
    const float* Wh2 = (const float*)d_in[9];
    const float* bh2 = (const float*)d_in[10];
    float* out = (float*)d_out;

    cudaFuncSetAttribute(edge_kernel_m, cudaFuncAttributeMaxDynamicSharedMemorySize, EDGE_SMEM);
    cudaFuncSetAttribute(fused_aux, cudaFuncAttributeMaxDynamicSharedMemorySize, GP_SMEM);
    cudaFuncSetAttribute(node_kernel_m, cudaFuncAttributeMaxDynamicSharedMemorySize, NODE_SMEM);

    prep_kernel<<<64, 256>>>(We1, We2, Wh1, Wh2);
    fused_aux<<<GP_BLOCKS + CV_BLOCKS, 256, GP_SMEM>>>(h, ei);   // convert || gemm_P
    edge_kernel_m<<<N_EDGES / 128, 256, EDGE_SMEM>>>(ea, be1, be2);
    node_kernel_m<<<(N_NODES + 63) / 64, 256, NODE_SMEM>>>(h, bh1, bh2, out);
}

// round 15
// speedup vs baseline: 1.2644x; 1.0344x over previous
#include <cuda_runtime.h>
#include <cstdint>

#define N_NODES 50000
#define N_EDGES 800000
#define DNODE   128
#define DEDGE   32
#define HID     128

typedef unsigned long long u64;

// ---------------- device-global scratch (no allocations allowed) ----------------
__device__ int   g_src[N_EDGES];
__device__ int   g_dst[N_EDGES];
__device__ float g_mi[(size_t)N_NODES * HID];      // 25.6 MB scatter target
__device__ float g_P[(size_t)N_NODES * 256];       // 51.2 MB: [h@W1a | h@W1b]
__device__ float g_W1r[288 * 128];                 // We1, tf32-rounded (RNA), [K][N]
__device__ float g_W2r[128 * 128];                 // We2, tf32-rounded (RNA), [K][N]
__device__ float g_Wh1hi[256 * 128];               // Wh1 split hi/lo (3xTF32)
__device__ float g_Wh1lo[256 * 128];
__device__ float g_Wh2hi[128 * 128];
__device__ float g_Wh2lo[128 * 128];

// ---------------- helpers ----------------
__device__ __forceinline__ uint32_t smem_u32(const void* p) {
    uint32_t a;
    asm("{ .reg .u64 t; cvta.to.shared.u64 t, %1; cvt.u32.u64 %0, t; }" : "=r"(a) : "l"(p));
    return a;
}
__device__ __forceinline__ uint32_t rna(float x) {
    uint32_t r; asm("cvt.rna.tf32.f32 %0, %1;" : "=r"(r) : "f"(x)); return r;
}

#define CP_ASYNC(ds, gp) \
    asm volatile("cp.async.cg.shared.global [%0], [%1], 16;" :: "r"(ds), "l"(gp))
#define CP_COMMIT() asm volatile("cp.async.commit_group;" ::: "memory")
#define CP_WAIT1()  asm volatile("cp.async.wait_group 1;" ::: "memory")
#define CP_WAIT0()  asm volatile("cp.async.wait_group 0;" ::: "memory")

#define MMA_TF32(C, a0, a1, a2, a3, b0, b1) \
    asm volatile("mma.sync.aligned.m16n8k8.row.col.f32.tf32.tf32.f32 " \
        "{%0,%1,%2,%3}, {%4,%5,%6,%7}, {%8,%9}, {%0,%1,%2,%3};" \
        : "+f"((C)[0]), "+f"((C)[1]), "+f"((C)[2]), "+f"((C)[3]) \
        : "r"(a0), "r"(a1), "r"(a2), "r"(a3), "r"(b0), "r"(b1))

// =================================================================
// Fused aux: blocks [0, CV_BLOCKS) = convert (index decode + zero g_mi),
// blocks [CV_BLOCKS, CV_BLOCKS+PR_BLOCKS) = prep (weight round/split).
// Both branches are tiny-smem -> no occupancy penalty (R14's mistake fixed).
// =================================================================
#define CV_BLOCKS 3125
#define PR_BLOCKS 64

__global__ void aux_kernel(const void* __restrict__ ei,
                           const float* __restrict__ W1, const float* __restrict__ W2,
                           const float* __restrict__ Wh1, const float* __restrict__ Wh2) {
    const int tid = threadIdx.x;
    if (blockIdx.x < CV_BLOCKS) {
        // ---------------- convert part (verbatim R11 body) ----------------
        __shared__ int s64;
        if (tid == 0) {
            const int* p = (const int*)ei;
            int all0 = 1;
            for (int s = 0; s < 256; s++)
                if (p[2 * s + 1] != 0) { all0 = 0; break; }
            s64 = all0;
        }
        __syncthreads();
        int i = blockIdx.x * 256 + tid;
        if (i < N_EDGES) {
            if (s64) {
                const long long* p = (const long long*)ei;
                g_src[i] = (int)p[i];
                g_dst[i] = (int)p[N_EDGES + i];
            } else {
                const int* p = (const int*)ei;
                g_src[i] = p[i];
                g_dst[i] = p[N_EDGES + i];
            }
        }
        size_t n4 = (size_t)N_NODES * HID / 4;
        float4 z = make_float4(0.f, 0.f, 0.f, 0.f);
        for (size_t j = (size_t)blockIdx.x * 256 + tid; j < n4;
             j += (size_t)CV_BLOCKS * 256)
            ((float4*)g_mi)[j] = z;
    } else {
        // ---------------- prep part (verbatim R11 body) ----------------
        int t = (blockIdx.x - CV_BLOCKS) * 256 + tid;
        int stride = PR_BLOCKS * 256;
        for (int i = t; i < 288 * 128; i += stride)
            g_W1r[i] = __uint_as_float(rna(W1[i]));
        for (int i = t; i < 128 * 128; i += stride)
            g_W2r[i] = __uint_as_float(rna(W2[i]));
        for (int i = t; i < 256 * 128; i += stride) {
            float w = Wh1[i];
            uint32_t hi = rna(w);
            g_Wh1hi[i] = __uint_as_float(hi);
            g_Wh1lo[i] = __uint_as_float(rna(w - __uint_as_float(hi)));
        }
        for (int i = t; i < 128 * 128; i += stride) {
            float w = Wh2[i];
            uint32_t hi = rna(w);
            g_Wh2hi[i] = __uint_as_float(hi);
            g_Wh2lo[i] = __uint_as_float(rna(w - __uint_as_float(hi)));
        }
    }
}

// =================================================================
// Precompute P = h @ [We1_a | We1_b]  (50k x 128 x 256, tf32 mma)
// =================================================================
#define GP_SMEM 98304

__global__ __launch_bounds__(256) void gemm_P(const float* __restrict__ h) {
    extern __shared__ char sm[];
    const uint32_t smb = smem_u32(sm);
    const int tid = threadIdx.x, lane = tid & 31, wid = tid >> 5;
    const int g = lane >> 2, t4 = lane & 3;
    const int m0 = (wid >> 2) * 64, n0 = (wid & 3) * 64;
    const int r0 = blockIdx.x * 128;

    auto issue_x = [&](int ch, int b) {
        uint32_t xb = smb + b * 16384;
#pragma unroll
        for (int i = 0; i < 4; i++) {
            int f = tid + i * 256;
            int row = f >> 3, q = f & 7;
            int gr = r0 + row; if (gr >= N_NODES) gr = 0;
            const float* gp = h + (size_t)gr * DNODE + ch * 32 + q * 4;
            uint32_t ds = xb + 4u * (uint32_t)(row * 32 + ((4 * q) ^ (4 * (row & 7))));
            CP_ASYNC(ds, gp);
        }
    };
    auto issue_w = [&](int ch, int b) {
        uint32_t wb = smb + 32768 + b * 32768;
#pragma unroll
        for (int i = 0; i < 8; i++) {
            int f = tid + i * 256;
            int k = f >> 6, n4 = f & 63;
            int n = 4 * n4;
            const float* gp = (n < 128)
                ? g_W1r + (size_t)(ch * 32 + k) * 128 + n
                : g_W1r + (size_t)(128 + ch * 32 + k) * 128 + (n - 128);
            uint32_t ds = wb + 4u * (uint32_t)(k * 256 + (n ^ (8 * (k & 3))));
            CP_ASYNC(ds, gp);
        }
    };

    float c[4][8][4];
#pragma unroll
    for (int mf = 0; mf < 4; mf++)
#pragma unroll
        for (int nf = 0; nf < 8; nf++)
#pragma unroll
            for (int j = 0; j < 4; j++) c[mf][nf][j] = 0.0f;

    issue_x(0, 0); issue_w(0, 0); CP_COMMIT();
    for (int ch = 0; ch < 4; ch++) {
        CP_WAIT0();
        __syncthreads();
        if (ch < 3) {
            issue_x(ch + 1, (ch + 1) & 1);
            issue_w(ch + 1, (ch + 1) & 1);
            CP_COMMIT();
        }
        const uint32_t* Xw = (const uint32_t*)sm + (ch & 1) * 4096;
        const uint32_t* Ww = (const uint32_t*)(sm + 32768) + (ch & 1) * 8192;
#pragma unroll
        for (int s = 0; s < 4; s++) {
            const int kb = 8 * s + t4;
            uint32_t b0r[8], b1r[8];
#pragma unroll
            for (int nf = 0; nf < 8; nf++) {
                int wc = (n0 + 8 * nf + g) ^ (8 * t4);
                b0r[nf] = Ww[kb * 256 + wc];
                b1r[nf] = Ww[(kb + 4) * 256 + wc];
            }
#pragma unroll
            for (int mf = 0; mf < 4; mf++) {
                int base = (m0 + mf * 16 + g) * 32;
                uint32_t a0 = Xw[base + (kb ^ (4 * g))];
                uint32_t a1 = Xw[base + 8 * 32 + (kb ^ (4 * g))];
                uint32_t a2 = Xw[base + ((kb + 4) ^ (4 * g))];
                uint32_t a3 = Xw[base + 8 * 32 + ((kb + 4) ^ (4 * g))];
#pragma unroll
                for (int nf = 0; nf < 8; nf++)
                    MMA_TF32(c[mf][nf], a0, a1, a2, a3, b0r[nf], b1r[nf]);
            }
        }
    }

#pragma unroll
    for (int mf = 0; mf < 4; mf++) {
        int r = m0 + mf * 16 + g;
#pragma unroll
        for (int nf = 0; nf < 8; nf++) {
            int col = n0 + 8 * nf + 2 * t4;
            if (r0 + r < N_NODES)
                *(float2*)(g_P + (size_t)(r0 + r) * 256 + col) =
                    make_float2(c[mf][nf][0], c[mf][nf][1]);
            if (r0 + r + 8 < N_NODES)
                *(float2*)(g_P + (size_t)(r0 + r + 8) * 256 + col) =
                    make_float2(c[mf][nf][2], c[mf][nf][3]);
        }
    }
}

// =================================================================
// Edge kernel (verbatim R11 — converged optimum):
// 128 edges/block, 256 thr, warp grid 4m x 2n (tile 32x64), 2 CTAs/SM,
// lean WAIT->sync->issue->compute schedule, early W2 prefetch.
// smem: Ys 64KB @0 (ea X-chunk overlays [0,16384)), W 2x16KB @65536,
//       sb1@98304, sb2@98816, sSrc@99328, sDst@99840
// =================================================================
#define EDGE_SMEM 100352

__global__ __launch_bounds__(256, 2) void edge_kernel_m(
    const float* __restrict__ ea,
    const float* __restrict__ b1g, const float* __restrict__ b2g)
{
    extern __shared__ char sm[];
    const uint32_t smb = smem_u32(sm);
    float* Ys  = (float*)sm;
    float* sb1 = (float*)(sm + 98304);
    float* sb2 = (float*)(sm + 98816);
    int*   sSrc = (int*)(sm + 99328);
    int*   sDst = (int*)(sm + 99840);

    const int tid  = threadIdx.x;
    const int lane = tid & 31, wid = tid >> 5;
    const int g    = lane >> 2, t4 = lane & 3;
    const int m0   = (wid >> 1) * 32;
    const int n0   = (wid & 1) * 64;
    const int e0   = blockIdx.x * 128;

    if (tid < 128) {
        sb1[tid] = b1g[tid];
        sb2[tid] = b2g[tid];
        sSrc[tid] = g_src[e0 + tid];
        sDst[tid] = g_dst[e0 + tid];
    }

    auto issue_w = [&](const float* W, int ch, int wb) {
        uint32_t wbase = smb + 65536 + wb * 16384;
#pragma unroll
        for (int i = 0; i < 4; i++) {
            int f = tid + i * 256;
            int k = f >> 5, n4 = f & 31;
            const float* gp = W + (size_t)(ch * 32 + k) * 128 + n4 * 4;
            uint32_t ds = wbase + 4u * (uint32_t)(k * 128 + ((4 * n4) ^ (8 * (k & 3))));
            CP_ASYNC(ds, gp);
        }
    };

    // group A: ea chunk + W1e (buf0)
#pragma unroll
    for (int i = 0; i < 4; i++) {
        int f = tid + i * 256;
        int row = f >> 3, q = f & 7;
        const float* gp = ea + (size_t)(e0 + row) * DEDGE + q * 4;
        uint32_t ds = smb + 4u * (uint32_t)(row * 32 + ((4 * q) ^ (4 * (row & 7))));
        CP_ASYNC(ds, gp);
    }
    issue_w(g_W1r, 8, 0);
    CP_COMMIT();
    // group B: W2 chunk0 (buf1) — prefetched across phase 1 + epilogue
    issue_w(g_W2r, 0, 1);
    CP_COMMIT();

    float c[2][8][4];
#pragma unroll
    for (int mf = 0; mf < 2; mf++)
#pragma unroll
        for (int nf = 0; nf < 8; nf++)
#pragma unroll
            for (int j = 0; j < 4; j++) c[mf][nf][j] = 0.0f;

    auto compute = [&](const uint32_t* Xw, int rstride, int cofs, const uint32_t* Ww) {
#pragma unroll
        for (int s = 0; s < 4; s++) {
            const int kb = 8 * s + t4;
            uint32_t b0r[8], b1r[8];
#pragma unroll
            for (int nf = 0; nf < 8; nf++) {
                int wc = (n0 + 8 * nf + g) ^ (8 * t4);
                b0r[nf] = Ww[kb * 128 + wc];
                b1r[nf] = Ww[(kb + 4) * 128 + wc];
            }
#pragma unroll
            for (int mf = 0; mf < 2; mf++) {
                int base = (m0 + mf * 16 + g) * rstride + cofs;
                uint32_t a0 = Xw[base + (kb ^ (4 * g))];
                uint32_t a1 = Xw[base + 8 * rstride + (kb ^ (4 * g))];
                uint32_t a2 = Xw[base + ((kb + 4) ^ (4 * g))];
                uint32_t a3 = Xw[base + 8 * rstride + ((kb + 4) ^ (4 * g))];
#pragma unroll
                for (int nf = 0; nf < 8; nf++)
                    MMA_TF32(c[mf][nf], a0, a1, a2, a3, b0r[nf], b1r[nf]);
            }
        }
    };

    // ======== phase 1: T = ea @ We1_e (K=32, W1e @ buf0) ========
    CP_WAIT1();                 // group A arrived (B may be in flight)
    __syncthreads();
    compute((const uint32_t*)sm, 32, 0, (const uint32_t*)(sm + 65536));
    __syncthreads();            // Xe + buf0 free

    // group C: W2 chunk1 -> buf0 (overlaps epilogue + P-merge)
    issue_w(g_W2r, 1, 0);
    CP_COMMIT();

    // epilogue A: write raw T into Ys (swizzled), zero accumulators
#pragma unroll
    for (int mf = 0; mf < 2; mf++) {
        int r0r = m0 + mf * 16 + g;
#pragma unroll
        for (int nf = 0; nf < 8; nf++) {
            int cc = n0 + 8 * nf + 2 * t4;
            int w = (cc & ~31) + ((cc & 31) ^ (4 * g));
            *(float2*)&Ys[r0r * 128 + w]       = make_float2(c[mf][nf][0], c[mf][nf][1]);
            *(float2*)&Ys[(r0r + 8) * 128 + w] = make_float2(c[mf][nf][2], c[mf][nf][3]);
#pragma unroll
            for (int j = 0; j < 4; j++) c[mf][nf][j] = 0.0f;
        }
    }
    __syncthreads();            // fragment-map writes -> row-map reads

    // P-merge: Y = relu(T + P[src].lo + P[dst].hi + b1)   (row-major float4)
#pragma unroll 4
    for (int i = 0; i < 16; i++) {
        int f = tid + i * 256;
        int row = f >> 5, c4 = f & 31;
        int w = row * 128 + (c4 >> 3) * 32 + ((4 * (c4 & 7)) ^ (4 * (row & 7)));
        float4 t = *(const float4*)&Ys[w];
        float4 ps = *(const float4*)(g_P + (size_t)sSrc[row] * 256 + 4 * c4);
        float4 pd = *(const float4*)(g_P + (size_t)sDst[row] * 256 + 128 + 4 * c4);
        float4 b = *(const float4*)&sb1[4 * c4];
        float4 y;
        y.x = fmaxf(t.x + ps.x + pd.x + b.x, 0.0f);
        y.y = fmaxf(t.y + ps.y + pd.y + b.y, 0.0f);
        y.z = fmaxf(t.z + ps.z + pd.z + b.z, 0.0f);
        y.w = fmaxf(t.w + ps.w + pd.w + b.w, 0.0f);
        *(float4*)&Ys[w] = y;
    }

    // ======== phase 2: K=128, chunks 0..3, buffers 1,0,1,0 ========
    // ch0 (buf1, group B)
    CP_WAIT1();                 // B arrived (C may pend)
    __syncthreads();            // publishes P-merge Ys + B's data; retires merge reads
    compute((const uint32_t*)sm, 128, 0, (const uint32_t*)(sm + 65536) + 4096);
    // ch1 (buf0, group C)
    CP_WAIT0();
    __syncthreads();
    issue_w(g_W2r, 2, 1); CP_COMMIT();   // group D -> buf1 (freed by sync)
    compute((const uint32_t*)sm, 128, 32, (const uint32_t*)(sm + 65536));
    // ch2 (buf1, group D)
    CP_WAIT0();
    __syncthreads();
    issue_w(g_W2r, 3, 0); CP_COMMIT();   // group E -> buf0
    compute((const uint32_t*)sm, 128, 64, (const uint32_t*)(sm + 65536) + 4096);
    // ch3 (buf0, group E)
    CP_WAIT0();
    __syncthreads();
    compute((const uint32_t*)sm, 128, 96, (const uint32_t*)(sm + 65536));
    __syncthreads();            // all warps done reading Ys

    // stage messages (+bias b2) into Ys
#pragma unroll
    for (int mf = 0; mf < 2; mf++) {
        int r0r = m0 + mf * 16 + g;
#pragma unroll
        for (int nf = 0; nf < 8; nf++) {
            int cc = n0 + 8 * nf + 2 * t4;
            float bb0 = sb2[cc], bb1 = sb2[cc + 1];
            int w = (cc & ~31) + ((cc & 31) ^ (4 * g));
            *(float2*)&Ys[r0r * 128 + w] =
                make_float2(c[mf][nf][0] + bb0, c[mf][nf][1] + bb1);
            *(float2*)&Ys[(r0r + 8) * 128 + w] =
                make_float2(c[mf][nf][2] + bb0, c[mf][nf][3] + bb1);
        }
    }
    __syncthreads();

    // coalesced vectorized scatter-add (one dst row per warp-instr)
#pragma unroll 4
    for (int i = 0; i < 16; i++) {
        int f = tid + i * 256;
        int row = f >> 5, c4 = f & 31;
        int w = row * 128 + (c4 >> 3) * 32 + ((4 * (c4 & 7)) ^ (4 * (row & 7)));
        float4 v = *(const float4*)&Ys[w];
        float* gp = g_mi + (size_t)sDst[row] * HID + 4 * c4;
        asm volatile("red.global.add.v4.f32 [%0], {%1,%2,%3,%4};"
                     :: "l"(gp), "f"(v.x), "f"(v.y), "f"(v.z), "f"(v.w) : "memory");
    }
}

// =================================================================
// Node MLP via 3xTF32 split mma — lean schedule (verbatim R11)
// =================================================================
#define NODE_SMEM 99328

__global__ __launch_bounds__(256, 2) void node_kernel_m(
    const float* __restrict__ h,
    const float* __restrict__ b1g, const float* __restrict__ b2g,
    float* __restrict__ out)
{
    extern __shared__ char sm[];
    const uint32_t smb = smem_u32(sm);
    float* Ys  = (float*)sm;
    float* sb1 = (float*)(sm + 98304);
    float* sb2 = (float*)(sm + 98816);

    const int tid  = threadIdx.x;
    const int lane = tid & 31, wid = tid >> 5;
    const int g    = lane >> 2, t4 = lane & 3;
    const int m0   = (wid >> 1) * 16;
    const int n0   = (wid & 1) * 64;
    const int r0   = blockIdx.x * 64;

    if (tid < 128) { sb1[tid] = b1g[tid]; sb2[tid] = b2g[tid]; }

    auto issue_x = [&](int ch, int b) {
        uint32_t xb = smb + b * 8192;
#pragma unroll
        for (int i = 0; i < 2; i++) {
            int f = tid + i * 256;
            int row = f >> 3, q = f & 7;
            int gr = r0 + row; if (gr >= N_NODES) gr = 0;
            const float* gp = (ch < 4)
                ? h    + (size_t)gr * DNODE + ch * 32 + q * 4
                : g_mi + (size_t)gr * HID   + (ch - 4) * 32 + q * 4;
            uint32_t ds = xb + 4u * (uint32_t)(row * 32 + ((4 * q) ^ (4 * (row & 7))));
            CP_ASYNC(ds, gp);
        }
    };
    auto issue_w = [&](const float* Whi, const float* Wlo, int ch, int b) {
        uint32_t base_hi = smb + 32768 + b * 32768;
#pragma unroll
        for (int i = 0; i < 4; i++) {
            int f = tid + i * 256;
            int k = f >> 5, n4 = f & 31;
            uint32_t off = 4u * (uint32_t)(k * 128 + ((4 * n4) ^ (8 * (k & 3))));
            CP_ASYNC(base_hi + off,         Whi + (size_t)(ch * 32 + k) * 128 + n4 * 4);
            CP_ASYNC(base_hi + 16384 + off, Wlo + (size_t)(ch * 32 + k) * 128 + n4 * 4);
        }
    };

    float c[8][4];
#pragma unroll
    for (int nf = 0; nf < 8; nf++)
#pragma unroll
        for (int j = 0; j < 4; j++) c[nf][j] = 0.0f;

    auto computeN = [&](const uint32_t* Xw, int rstride, int cofs,
                        const uint32_t* Whi, const uint32_t* Wlo) {
#pragma unroll
        for (int s = 0; s < 4; s++) {
            const int kb = 8 * s + t4;
            int base0 = (m0 + g) * rstride + cofs;
            int base1 = (m0 + 8 + g) * rstride + cofs;
            float x0 = __uint_as_float(Xw[base0 + (kb ^ (4 * g))]);
            float x1 = __uint_as_float(Xw[base1 + (kb ^ (4 * g))]);
            float x2 = __uint_as_float(Xw[base0 + ((kb + 4) ^ (4 * g))]);
            float x3 = __uint_as_float(Xw[base1 + ((kb + 4) ^ (4 * g))]);
            uint32_t h0 = rna(x0), h1 = rna(x1), h2 = rna(x2), h3 = rna(x3);
            uint32_t l0 = rna(x0 - __uint_as_float(h0));
            uint32_t l1 = rna(x1 - __uint_as_float(h1));
            uint32_t l2 = rna(x2 - __uint_as_float(h2));
            uint32_t l3 = rna(x3 - __uint_as_float(h3));
#pragma unroll
            for (int nf = 0; nf < 8; nf++) {
                int wc = (n0 + 8 * nf + g) ^ (8 * t4);
                uint32_t bh0 = Whi[kb * 128 + wc], bh1 = Whi[(kb + 4) * 128 + wc];
                uint32_t bl0 = Wlo[kb * 128 + wc], bl1 = Wlo[(kb + 4) * 128 + wc];
                MMA_TF32(c[nf], h0, h1, h2, h3, bh0, bh1);
                MMA_TF32(c[nf], l0, l1, l2, l3, bh0, bh1);
                MMA_TF32(c[nf], h0, h1, h2, h3, bl0, bl1);
            }
        }
    };

    // ======== layer 1: K=256, 8 chunks — one sync per chunk ========
    issue_x(0, 0); issue_w(g_Wh1hi, g_Wh1lo, 0, 0); CP_COMMIT();
    for (int ch = 0; ch < 8; ch++) {
        CP_WAIT0();
        __syncthreads();
        if (ch < 7) {
            issue_x(ch + 1, (ch + 1) & 1);
            issue_w(g_Wh1hi, g_Wh1lo, ch + 1, (ch + 1) & 1);
            CP_COMMIT();
        }
        computeN((const uint32_t*)sm + (ch & 1) * 2048, 32, 0,
                 (const uint32_t*)(sm + 32768 + (ch & 1) * 32768),
                 (const uint32_t*)(sm + 32768 + (ch & 1) * 32768 + 16384));
    }
    __syncthreads();   // last compute done before Ys (overlaps X bufs) is written

    // ---- epilogue 1: relu(x + b1) -> Ys (swizzled), zero c ----
#pragma unroll
    for (int nf = 0; nf < 8; nf++) {
        int cc = n0 + 8 * nf + 2 * t4;
        float bb0 = sb1[cc], bb1 = sb1[cc + 1];
        int w = (cc & ~31) + ((cc & 31) ^ (4 * g));
        *(float2*)&Ys[(m0 + g) * 128 + w] =
            make_float2(fmaxf(c[nf][0] + bb0, 0.0f), fmaxf(c[nf][1] + bb1, 0.0f));
        *(float2*)&Ys[(m0 + 8 + g) * 128 + w] =
            make_float2(fmaxf(c[nf][2] + bb0, 0.0f), fmaxf(c[nf][3] + bb1, 0.0f));
#pragma unroll
        for (int j = 0; j < 4; j++) c[nf][j] = 0.0f;
    }
    issue_w(g_Wh2hi, g_Wh2lo, 0, 0); CP_COMMIT();

    // ======== layer 2: K=128, 4 chunks — one sync per chunk ========
    for (int ch = 0; ch < 4; ch++) {
        CP_WAIT0();
        __syncthreads();   // ch0's sync also publishes epilogue Ys writes
        if (ch < 3) {
            issue_w(g_Wh2hi, g_Wh2lo, ch + 1, (ch + 1) & 1);
            CP_COMMIT();
        }
        computeN((const uint32_t*)sm, 128, ch * 32,
                 (const uint32_t*)(sm + 32768 + (ch & 1) * 32768),
                 (const uint32_t*)(sm + 32768 + (ch & 1) * 32768 + 16384));
    }

    // ---- store out = c + b2 (own accumulators only) ----
#pragma unroll
    for (int nf = 0; nf < 8; nf++) {
        int cc = n0 + 8 * nf + 2 * t4;
        float bb0 = sb2[cc], bb1 = sb2[cc + 1];
        int ra = r0 + m0 + g, rb = ra + 8;
        if (ra < N_NODES)
            *(float2*)(out + (size_t)ra * 128 + cc) =
                make_float2(c[nf][0] + bb0, c[nf][1] + bb1);
        if (rb < N_NODES)
            *(float2*)(out + (size_t)rb * 128 + cc) =
                make_float2(c[nf][2] + bb0, c[nf][3] + bb1);
    }
}

// =================================================================
extern "C" void kernel_launch(void* const* d_in, const int* in_sizes, int n_in,
                              void* d_out, int out_size) {
    const float* h   = (const float*)d_in[0];
    const void*  ei  = d_in[1];
    const float* ea  = (const float*)d_in[2];
    const float* We1 = (const float*)d_in[3];
    const float* be1 = (const float*)d_in[4];
    const float* We2 = (const float*)d_in[5];
    const float* be2 = (const float*)d_in[6];
    const float* Wh1 = (const float*)d_in[7];
    const float* bh1 = (const float*)d_in[8];
    const float* Wh2 = (const float*)d_in[9];
    const float* bh2 = (const float*)d_in[10];
    float* out = (float*)d_out;

    cudaFuncSetAttribute(edge_kernel_m, cudaFuncAttributeMaxDynamicSharedMemorySize, EDGE_SMEM);
    cudaFuncSetAttribute(gemm_P, cudaFuncAttributeMaxDynamicSharedMemorySize, GP_SMEM);
    cudaFuncSetAttribute(node_kernel_m, cudaFuncAttributeMaxDynamicSharedMemorySize, NODE_SMEM);

    aux_kernel<<<CV_BLOCKS + PR_BLOCKS, 256>>>(ei, We1, We2, Wh1, Wh2);  // convert || prep
    gemm_P<<<(N_NODES + 127) / 128, 256, GP_SMEM>>>(h);
    edge_kernel_m<<<N_EDGES / 128, 256, EDGE_SMEM>>>(ea, be1, be2);
    node_kernel_m<<<(N_NODES + 63) / 64, 256, NODE_SMEM>>>(h, bh1, bh2, out);
}

// round 16
// speedup vs baseline: 1.3386x; 1.0587x over previous
#include <cuda_runtime.h>
#include <cstdint>

#define N_NODES 50000
#define N_EDGES 800000
#define DNODE   128
#define DEDGE   32
#define HID     128

typedef unsigned long long u64;

// ---------------- device-global scratch (no allocations allowed) ----------------
__device__ int   g_src[N_EDGES];
__device__ int   g_dst[N_EDGES];
__device__ float g_mi[(size_t)N_NODES * HID];      // 25.6 MB scatter target
__device__ float g_P[(size_t)N_NODES * 256];       // 51.2 MB: [h@W1a | h@W1b]
__device__ float g_W1r[288 * 128];                 // We1, tf32-rounded (RNA), [K][N]
__device__ float g_W2r[128 * 128];                 // We2, tf32-rounded (RNA), [K][N]
__device__ float g_Wh1hi[256 * 128];               // Wh1 tf32-rounded (2xTF32 node path)
__device__ float g_Wh2hi[128 * 128];               // Wh2 tf32-rounded

// ---------------- helpers ----------------
__device__ __forceinline__ uint32_t smem_u32(const void* p) {
    uint32_t a;
    asm("{ .reg .u64 t; cvta.to.shared.u64 t, %1; cvt.u32.u64 %0, t; }" : "=r"(a) : "l"(p));
    return a;
}
__device__ __forceinline__ uint32_t rna(float x) {
    uint32_t r; asm("cvt.rna.tf32.f32 %0, %1;" : "=r"(r) : "f"(x)); return r;
}

#define CP_ASYNC(ds, gp) \
    asm volatile("cp.async.cg.shared.global [%0], [%1], 16;" :: "r"(ds), "l"(gp))
#define CP_COMMIT() asm volatile("cp.async.commit_group;" ::: "memory")
#define CP_WAIT1()  asm volatile("cp.async.wait_group 1;" ::: "memory")
#define CP_WAIT0()  asm volatile("cp.async.wait_group 0;" ::: "memory")

#define MMA_TF32(C, a0, a1, a2, a3, b0, b1) \
    asm volatile("mma.sync.aligned.m16n8k8.row.col.f32.tf32.tf32.f32 " \
        "{%0,%1,%2,%3}, {%4,%5,%6,%7}, {%8,%9}, {%0,%1,%2,%3};" \
        : "+f"((C)[0]), "+f"((C)[1]), "+f"((C)[2]), "+f"((C)[3]) \
        : "r"(a0), "r"(a1), "r"(a2), "r"(a3), "r"(b0), "r"(b1))

// =================================================================
// Fused aux: blocks [0, CV_BLOCKS) = convert (index decode + zero g_mi),
// blocks [CV_BLOCKS, CV_BLOCKS+PR_BLOCKS) = prep (weight rounding).
// =================================================================
#define CV_BLOCKS 3125
#define PR_BLOCKS 64

__global__ void aux_kernel(const void* __restrict__ ei,
                           const float* __restrict__ W1, const float* __restrict__ W2,
                           const float* __restrict__ Wh1, const float* __restrict__ Wh2) {
    const int tid = threadIdx.x;
    if (blockIdx.x < CV_BLOCKS) {
        // ---------------- convert part ----------------
        __shared__ int s64;
        if (tid == 0) {
            const int* p = (const int*)ei;
            int all0 = 1;
            for (int s = 0; s < 256; s++)
                if (p[2 * s + 1] != 0) { all0 = 0; break; }
            s64 = all0;
        }
        __syncthreads();
        int i = blockIdx.x * 256 + tid;
        if (i < N_EDGES) {
            if (s64) {
                const long long* p = (const long long*)ei;
                g_src[i] = (int)p[i];
                g_dst[i] = (int)p[N_EDGES + i];
            } else {
                const int* p = (const int*)ei;
                g_src[i] = p[i];
                g_dst[i] = p[N_EDGES + i];
            }
        }
        size_t n4 = (size_t)N_NODES * HID / 4;
        float4 z = make_float4(0.f, 0.f, 0.f, 0.f);
        for (size_t j = (size_t)blockIdx.x * 256 + tid; j < n4;
             j += (size_t)CV_BLOCKS * 256)
            ((float4*)g_mi)[j] = z;
    } else {
        // ---------------- prep part (hi-only node weights) ----------------
        int t = (blockIdx.x - CV_BLOCKS) * 256 + tid;
        int stride = PR_BLOCKS * 256;
        for (int i = t; i < 288 * 128; i += stride)
            g_W1r[i] = __uint_as_float(rna(W1[i]));
        for (int i = t; i < 128 * 128; i += stride)
            g_W2r[i] = __uint_as_float(rna(W2[i]));
        for (int i = t; i < 256 * 128; i += stride)
            g_Wh1hi[i] = __uint_as_float(rna(Wh1[i]));
        for (int i = t; i < 128 * 128; i += stride)
            g_Wh2hi[i] = __uint_as_float(rna(Wh2[i]));
    }
}

// =================================================================
// Precompute P = h @ [We1_a | We1_b]  (50k x 128 x 256, tf32 mma)
// =================================================================
#define GP_SMEM 98304

__global__ __launch_bounds__(256) void gemm_P(const float* __restrict__ h) {
    extern __shared__ char sm[];
    const uint32_t smb = smem_u32(sm);
    const int tid = threadIdx.x, lane = tid & 31, wid = tid >> 5;
    const int g = lane >> 2, t4 = lane & 3;
    const int m0 = (wid >> 2) * 64, n0 = (wid & 3) * 64;
    const int r0 = blockIdx.x * 128;

    auto issue_x = [&](int ch, int b) {
        uint32_t xb = smb + b * 16384;
#pragma unroll
        for (int i = 0; i < 4; i++) {
            int f = tid + i * 256;
            int row = f >> 3, q = f & 7;
            int gr = r0 + row; if (gr >= N_NODES) gr = 0;
            const float* gp = h + (size_t)gr * DNODE + ch * 32 + q * 4;
            uint32_t ds = xb + 4u * (uint32_t)(row * 32 + ((4 * q) ^ (4 * (row & 7))));
            CP_ASYNC(ds, gp);
        }
    };
    auto issue_w = [&](int ch, int b) {
        uint32_t wb = smb + 32768 + b * 32768;
#pragma unroll
        for (int i = 0; i < 8; i++) {
            int f = tid + i * 256;
            int k = f >> 6, n4 = f & 63;
            int n = 4 * n4;
            const float* gp = (n < 128)
                ? g_W1r + (size_t)(ch * 32 + k) * 128 + n
                : g_W1r + (size_t)(128 + ch * 32 + k) * 128 + (n - 128);
            uint32_t ds = wb + 4u * (uint32_t)(k * 256 + (n ^ (8 * (k & 3))));
            CP_ASYNC(ds, gp);
        }
    };

    float c[4][8][4];
#pragma unroll
    for (int mf = 0; mf < 4; mf++)
#pragma unroll
        for (int nf = 0; nf < 8; nf++)
#pragma unroll
            for (int j = 0; j < 4; j++) c[mf][nf][j] = 0.0f;

    issue_x(0, 0); issue_w(0, 0); CP_COMMIT();
    for (int ch = 0; ch < 4; ch++) {
        CP_WAIT0();
        __syncthreads();
        if (ch < 3) {
            issue_x(ch + 1, (ch + 1) & 1);
            issue_w(ch + 1, (ch + 1) & 1);
            CP_COMMIT();
        }
        const uint32_t* Xw = (const uint32_t*)sm + (ch & 1) * 4096;
        const uint32_t* Ww = (const uint32_t*)(sm + 32768) + (ch & 1) * 8192;
#pragma unroll
        for (int s = 0; s < 4; s++) {
            const int kb = 8 * s + t4;
            uint32_t b0r[8], b1r[8];
#pragma unroll
            for (int nf = 0; nf < 8; nf++) {
                int wc = (n0 + 8 * nf + g) ^ (8 * t4);
                b0r[nf] = Ww[kb * 256 + wc];
                b1r[nf] = Ww[(kb + 4) * 256 + wc];
            }
#pragma unroll
            for (int mf = 0; mf < 4; mf++) {
                int base = (m0 + mf * 16 + g) * 32;
                uint32_t a0 = Xw[base + (kb ^ (4 * g))];
                uint32_t a1 = Xw[base + 8 * 32 + (kb ^ (4 * g))];
                uint32_t a2 = Xw[base + ((kb + 4) ^ (4 * g))];
                uint32_t a3 = Xw[base + 8 * 32 + ((kb + 4) ^ (4 * g))];
#pragma unroll
                for (int nf = 0; nf < 8; nf++)
                    MMA_TF32(c[mf][nf], a0, a1, a2, a3, b0r[nf], b1r[nf]);
            }
        }
    }

#pragma unroll
    for (int mf = 0; mf < 4; mf++) {
        int r = m0 + mf * 16 + g;
#pragma unroll
        for (int nf = 0; nf < 8; nf++) {
            int col = n0 + 8 * nf + 2 * t4;
            if (r0 + r < N_NODES)
                *(float2*)(g_P + (size_t)(r0 + r) * 256 + col) =
                    make_float2(c[mf][nf][0], c[mf][nf][1]);
            if (r0 + r + 8 < N_NODES)
                *(float2*)(g_P + (size_t)(r0 + r + 8) * 256 + col) =
                    make_float2(c[mf][nf][2], c[mf][nf][3]);
        }
    }
}

// =================================================================
// Edge kernel (verbatim R11/R15 — converged optimum)
// =================================================================
#define EDGE_SMEM 100352

__global__ __launch_bounds__(256, 2) void edge_kernel_m(
    const float* __restrict__ ea,
    const float* __restrict__ b1g, const float* __restrict__ b2g)
{
    extern __shared__ char sm[];
    const uint32_t smb = smem_u32(sm);
    float* Ys  = (float*)sm;
    float* sb1 = (float*)(sm + 98304);
    float* sb2 = (float*)(sm + 98816);
    int*   sSrc = (int*)(sm + 99328);
    int*   sDst = (int*)(sm + 99840);

    const int tid  = threadIdx.x;
    const int lane = tid & 31, wid = tid >> 5;
    const int g    = lane >> 2, t4 = lane & 3;
    const int m0   = (wid >> 1) * 32;
    const int n0   = (wid & 1) * 64;
    const int e0   = blockIdx.x * 128;

    if (tid < 128) {
        sb1[tid] = b1g[tid];
        sb2[tid] = b2g[tid];
        sSrc[tid] = g_src[e0 + tid];
        sDst[tid] = g_dst[e0 + tid];
    }

    auto issue_w = [&](const float* W, int ch, int wb) {
        uint32_t wbase = smb + 65536 + wb * 16384;
#pragma unroll
        for (int i = 0; i < 4; i++) {
            int f = tid + i * 256;
            int k = f >> 5, n4 = f & 31;
            const float* gp = W + (size_t)(ch * 32 + k) * 128 + n4 * 4;
            uint32_t ds = wbase + 4u * (uint32_t)(k * 128 + ((4 * n4) ^ (8 * (k & 3))));
            CP_ASYNC(ds, gp);
        }
    };

    // group A: ea chunk + W1e (buf0)
#pragma unroll
    for (int i = 0; i < 4; i++) {
        int f = tid + i * 256;
        int row = f >> 3, q = f & 7;
        const float* gp = ea + (size_t)(e0 + row) * DEDGE + q * 4;
        uint32_t ds = smb + 4u * (uint32_t)(row * 32 + ((4 * q) ^ (4 * (row & 7))));
        CP_ASYNC(ds, gp);
    }
    issue_w(g_W1r, 8, 0);
    CP_COMMIT();
    // group B: W2 chunk0 (buf1) — prefetched across phase 1 + epilogue
    issue_w(g_W2r, 0, 1);
    CP_COMMIT();

    float c[2][8][4];
#pragma unroll
    for (int mf = 0; mf < 2; mf++)
#pragma unroll
        for (int nf = 0; nf < 8; nf++)
#pragma unroll
            for (int j = 0; j < 4; j++) c[mf][nf][j] = 0.0f;

    auto compute = [&](const uint32_t* Xw, int rstride, int cofs, const uint32_t* Ww) {
#pragma unroll
        for (int s = 0; s < 4; s++) {
            const int kb = 8 * s + t4;
            uint32_t b0r[8], b1r[8];
#pragma unroll
            for (int nf = 0; nf < 8; nf++) {
                int wc = (n0 + 8 * nf + g) ^ (8 * t4);
                b0r[nf] = Ww[kb * 128 + wc];
                b1r[nf] = Ww[(kb + 4) * 128 + wc];
            }
#pragma unroll
            for (int mf = 0; mf < 2; mf++) {
                int base = (m0 + mf * 16 + g) * rstride + cofs;
                uint32_t a0 = Xw[base + (kb ^ (4 * g))];
                uint32_t a1 = Xw[base + 8 * rstride + (kb ^ (4 * g))];
                uint32_t a2 = Xw[base + ((kb + 4) ^ (4 * g))];
                uint32_t a3 = Xw[base + 8 * rstride + ((kb + 4) ^ (4 * g))];
#pragma unroll
                for (int nf = 0; nf < 8; nf++)
                    MMA_TF32(c[mf][nf], a0, a1, a2, a3, b0r[nf], b1r[nf]);
            }
        }
    };

    // ======== phase 1: T = ea @ We1_e (K=32, W1e @ buf0) ========
    CP_WAIT1();
    __syncthreads();
    compute((const uint32_t*)sm, 32, 0, (const uint32_t*)(sm + 65536));
    __syncthreads();

    // group C: W2 chunk1 -> buf0 (overlaps epilogue + P-merge)
    issue_w(g_W2r, 1, 0);
    CP_COMMIT();

    // epilogue A: write raw T into Ys (swizzled), zero accumulators
#pragma unroll
    for (int mf = 0; mf < 2; mf++) {
        int r0r = m0 + mf * 16 + g;
#pragma unroll
        for (int nf = 0; nf < 8; nf++) {
            int cc = n0 + 8 * nf + 2 * t4;
            int w = (cc & ~31) + ((cc & 31) ^ (4 * g));
            *(float2*)&Ys[r0r * 128 + w]       = make_float2(c[mf][nf][0], c[mf][nf][1]);
            *(float2*)&Ys[(r0r + 8) * 128 + w] = make_float2(c[mf][nf][2], c[mf][nf][3]);
#pragma unroll
            for (int j = 0; j < 4; j++) c[mf][nf][j] = 0.0f;
        }
    }
    __syncthreads();

    // P-merge: Y = relu(T + P[src].lo + P[dst].hi + b1)   (row-major float4)
#pragma unroll 4
    for (int i = 0; i < 16; i++) {
        int f = tid + i * 256;
        int row = f >> 5, c4 = f & 31;
        int w = row * 128 + (c4 >> 3) * 32 + ((4 * (c4 & 7)) ^ (4 * (row & 7)));
        float4 t = *(const float4*)&Ys[w];
        float4 ps = *(const float4*)(g_P + (size_t)sSrc[row] * 256 + 4 * c4);
        float4 pd = *(const float4*)(g_P + (size_t)sDst[row] * 256 + 128 + 4 * c4);
        float4 b = *(const float4*)&sb1[4 * c4];
        float4 y;
        y.x = fmaxf(t.x + ps.x + pd.x + b.x, 0.0f);
        y.y = fmaxf(t.y + ps.y + pd.y + b.y, 0.0f);
        y.z = fmaxf(t.z + ps.z + pd.z + b.z, 0.0f);
        y.w = fmaxf(t.w + ps.w + pd.w + b.w, 0.0f);
        *(float4*)&Ys[w] = y;
    }

    // ======== phase 2: K=128, chunks 0..3, buffers 1,0,1,0 ========
    CP_WAIT1();
    __syncthreads();
    compute((const uint32_t*)sm, 128, 0, (const uint32_t*)(sm + 65536) + 4096);
    CP_WAIT0();
    __syncthreads();
    issue_w(g_W2r, 2, 1); CP_COMMIT();
    compute((const uint32_t*)sm, 128, 32, (const uint32_t*)(sm + 65536));
    CP_WAIT0();
    __syncthreads();
    issue_w(g_W2r, 3, 0); CP_COMMIT();
    compute((const uint32_t*)sm, 128, 64, (const uint32_t*)(sm + 65536) + 4096);
    CP_WAIT0();
    __syncthreads();
    compute((const uint32_t*)sm, 128, 96, (const uint32_t*)(sm + 65536));
    __syncthreads();

    // stage messages (+bias b2) into Ys
#pragma unroll
    for (int mf = 0; mf < 2; mf++) {
        int r0r = m0 + mf * 16 + g;
#pragma unroll
        for (int nf = 0; nf < 8; nf++) {
            int cc = n0 + 8 * nf + 2 * t4;
            float bb0 = sb2[cc], bb1 = sb2[cc + 1];
            int w = (cc & ~31) + ((cc & 31) ^ (4 * g));
            *(float2*)&Ys[r0r * 128 + w] =
                make_float2(c[mf][nf][0] + bb0, c[mf][nf][1] + bb1);
            *(float2*)&Ys[(r0r + 8) * 128 + w] =
                make_float2(c[mf][nf][2] + bb0, c[mf][nf][3] + bb1);
        }
    }
    __syncthreads();

    // coalesced vectorized scatter-add
#pragma unroll 4
    for (int i = 0; i < 16; i++) {
        int f = tid + i * 256;
        int row = f >> 5, c4 = f & 31;
        int w = row * 128 + (c4 >> 3) * 32 + ((4 * (c4 & 7)) ^ (4 * (row & 7)));
        float4 v = *(const float4*)&Ys[w];
        float* gp = g_mi + (size_t)sDst[row] * HID + 4 * c4;
        asm volatile("red.global.add.v4.f32 [%0], {%1,%2,%3,%4};"
                     :: "l"(gp), "f"(v.x), "f"(v.y), "f"(v.z), "f"(v.w) : "memory");
    }
}

// =================================================================
// Node MLP via 2xTF32 split mma: out ≈ (x_hi + x_lo) @ w_hi.
// Only error vs fp32 is x @ w_lo (one-operand tf32, ~2.5-3.5e-4).
// Half the W traffic and 2/3 the MMAs of the R15 node kernel.
// smem: Ys 32KB @0 (X chunks overlay [0,16384)), Whi 2x16KB @32768,
//       sb1@65536, sb2@66048
// =================================================================
#define NODE_SMEM 66560

__global__ __launch_bounds__(256, 2) void node_kernel_m(
    const float* __restrict__ h,
    const float* __restrict__ b1g, const float* __restrict__ b2g,
    float* __restrict__ out)
{
    extern __shared__ char sm[];
    const uint32_t smb = smem_u32(sm);
    float* Ys  = (float*)sm;
    float* sb1 = (float*)(sm + 65536);
    float* sb2 = (float*)(sm + 66048);

    const int tid  = threadIdx.x;
    const int lane = tid & 31, wid = tid >> 5;
    const int g    = lane >> 2, t4 = lane & 3;
    const int m0   = (wid >> 1) * 16;
    const int n0   = (wid & 1) * 64;
    const int r0   = blockIdx.x * 64;

    if (tid < 128) { sb1[tid] = b1g[tid]; sb2[tid] = b2g[tid]; }

    auto issue_x = [&](int ch, int b) {
        uint32_t xb = smb + b * 8192;
#pragma unroll
        for (int i = 0; i < 2; i++) {
            int f = tid + i * 256;
            int row = f >> 3, q = f & 7;
            int gr = r0 + row; if (gr >= N_NODES) gr = 0;
            const float* gp = (ch < 4)
                ? h    + (size_t)gr * DNODE + ch * 32 + q * 4
                : g_mi + (size_t)gr * HID   + (ch - 4) * 32 + q * 4;
            uint32_t ds = xb + 4u * (uint32_t)(row * 32 + ((4 * q) ^ (4 * (row & 7))));
            CP_ASYNC(ds, gp);
        }
    };
    auto issue_w = [&](const float* Whi, int ch, int b) {
        uint32_t base_hi = smb + 32768 + b * 16384;
#pragma unroll
        for (int i = 0; i < 4; i++) {
            int f = tid + i * 256;
            int k = f >> 5, n4 = f & 31;
            uint32_t off = 4u * (uint32_t)(k * 128 + ((4 * n4) ^ (8 * (k & 3))));
            CP_ASYNC(base_hi + off, Whi + (size_t)(ch * 32 + k) * 128 + n4 * 4);
        }
    };

    float c[8][4];
#pragma unroll
    for (int nf = 0; nf < 8; nf++)
#pragma unroll
        for (int j = 0; j < 4; j++) c[nf][j] = 0.0f;

    auto computeN = [&](const uint32_t* Xw, int rstride, int cofs,
                        const uint32_t* Whi) {
#pragma unroll
        for (int s = 0; s < 4; s++) {
            const int kb = 8 * s + t4;
            int base0 = (m0 + g) * rstride + cofs;
            int base1 = (m0 + 8 + g) * rstride + cofs;
            float x0 = __uint_as_float(Xw[base0 + (kb ^ (4 * g))]);
            float x1 = __uint_as_float(Xw[base1 + (kb ^ (4 * g))]);
            float x2 = __uint_as_float(Xw[base0 + ((kb + 4) ^ (4 * g))]);
            float x3 = __uint_as_float(Xw[base1 + ((kb + 4) ^ (4 * g))]);
            uint32_t h0 = rna(x0), h1 = rna(x1), h2 = rna(x2), h3 = rna(x3);
            uint32_t l0 = rna(x0 - __uint_as_float(h0));
            uint32_t l1 = rna(x1 - __uint_as_float(h1));
            uint32_t l2 = rna(x2 - __uint_as_float(h2));
            uint32_t l3 = rna(x3 - __uint_as_float(h3));
#pragma unroll
            for (int nf = 0; nf < 8; nf++) {
                int wc = (n0 + 8 * nf + g) ^ (8 * t4);
                uint32_t bh0 = Whi[kb * 128 + wc], bh1 = Whi[(kb + 4) * 128 + wc];
                MMA_TF32(c[nf], h0, h1, h2, h3, bh0, bh1);
                MMA_TF32(c[nf], l0, l1, l2, l3, bh0, bh1);
            }
        }
    };

    // ======== layer 1: K=256, 8 chunks — one sync per chunk ========
    issue_x(0, 0); issue_w(g_Wh1hi, 0, 0); CP_COMMIT();
    for (int ch = 0; ch < 8; ch++) {
        CP_WAIT0();
        __syncthreads();
        if (ch < 7) {
            issue_x(ch + 1, (ch + 1) & 1);
            issue_w(g_Wh1hi, ch + 1, (ch + 1) & 1);
            CP_COMMIT();
        }
        computeN((const uint32_t*)sm + (ch & 1) * 2048, 32, 0,
                 (const uint32_t*)(sm + 32768 + (ch & 1) * 16384));
    }
    __syncthreads();   // last compute done before Ys (overlaps X bufs) is written

    // ---- epilogue 1: relu(x + b1) -> Ys (swizzled), zero c ----
#pragma unroll
    for (int nf = 0; nf < 8; nf++) {
        int cc = n0 + 8 * nf + 2 * t4;
        float bb0 = sb1[cc], bb1 = sb1[cc + 1];
        int w = (cc & ~31) + ((cc & 31) ^ (4 * g));
        *(float2*)&Ys[(m0 + g) * 128 + w] =
            make_float2(fmaxf(c[nf][0] + bb0, 0.0f), fmaxf(c[nf][1] + bb1, 0.0f));
        *(float2*)&Ys[(m0 + 8 + g) * 128 + w] =
            make_float2(fmaxf(c[nf][2] + bb0, 0.0f), fmaxf(c[nf][3] + bb1, 0.0f));
#pragma unroll
        for (int j = 0; j < 4; j++) c[nf][j] = 0.0f;
    }
    issue_w(g_Wh2hi, 0, 0); CP_COMMIT();

    // ======== layer 2: K=128, 4 chunks — one sync per chunk ========
    for (int ch = 0; ch < 4; ch++) {
        CP_WAIT0();
        __syncthreads();   // ch0's sync also publishes epilogue Ys writes
        if (ch < 3) {
            issue_w(g_Wh2hi, ch + 1, (ch + 1) & 1);
            CP_COMMIT();
        }
        computeN((const uint32_t*)sm, 128, ch * 32,
                 (const uint32_t*)(sm + 32768 + (ch & 1) * 16384));
    }

    // ---- store out = c + b2 (own accumulators only) ----
#pragma unroll
    for (int nf = 0; nf < 8; nf++) {
        int cc = n0 + 8 * nf + 2 * t4;
        float bb0 = sb2[cc], bb1 = sb2[cc + 1];
        int ra = r0 + m0 + g, rb = ra + 8;
        if (ra < N_NODES)
            *(float2*)(out + (size_t)ra * 128 + cc) =
                make_float2(c[nf][0] + bb0, c[nf][1] + bb1);
        if (rb < N_NODES)
            *(float2*)(out + (size_t)rb * 128 + cc) =
                make_float2(c[nf][2] + bb0, c[nf][3] + bb1);
    }
}

// =================================================================
extern "C" void kernel_launch(void* const* d_in, const int* in_sizes, int n_in,
                              void* d_out, int out_size) {
    const float* h   = (const float*)d_in[0];
    const void*  ei  = d_in[1];
    const float* ea  = (const float*)d_in[2];
    const float* We1 = (const float*)d_in[3];
    const float* be1 = (const float*)d_in[4];
    const float* We2 = (const float*)d_in[5];
    const float* be2 = (const float*)d_in[6];
    const float* Wh1 = (const float*)d_in[7];
    const float* bh1 = (const float*)d_in[8];
    const float* Wh2 = (const float*)d_in[9];
    const float* bh2 = (const float*)d_in[10];
    float* out = (float*)d_out;

    cudaFuncSetAttribute(edge_kernel_m, cudaFuncAttributeMaxDynamicSharedMemorySize, EDGE_SMEM);
    cudaFuncSetAttribute(gemm_P, cudaFuncAttributeMaxDynamicSharedMemorySize, GP_SMEM);
    cudaFuncSetAttribute(node_kernel_m, cudaFuncAttributeMaxDynamicSharedMemorySize, NODE_SMEM);

    aux_kernel<<<CV_BLOCKS + PR_BLOCKS, 256>>>(ei, We1, We2, Wh1, Wh2);  // convert || prep
    gemm_P<<<(N_NODES + 127) / 128, 256, GP_SMEM>>>(h);
    edge_kernel_m<<<N_EDGES / 128, 256, EDGE_SMEM>>>(ea, be1, be2);
    node_kernel_m<<<(N_NODES + 63) / 64, 256, NODE_SMEM>>>(h, bh1, bh2, out);
}

// round 17
// speedup vs baseline: 1.3836x; 1.0337x over previous
#include <cuda_runtime.h>
#include <cstdint>

#define N_NODES 50000
#define N_EDGES 800000
#define DNODE   128
#define DEDGE   32
#define HID     128

typedef unsigned long long u64;

// ---------------- device-global scratch (no allocations allowed) ----------------
__device__ int   g_src[N_EDGES];
__device__ int   g_dst[N_EDGES];
__device__ float g_mi[(size_t)N_NODES * HID];      // 25.6 MB scatter target
__device__ float g_P[(size_t)N_NODES * 256];       // 51.2 MB: [h@W1a | h@W1b]
__device__ float g_W1r[288 * 128];                 // We1, tf32-rounded (RNA), [K][N]
__device__ float g_W2r[128 * 128];                 // We2, tf32-rounded (RNA), [K][N]
__device__ float g_Wh1hi[256 * 128];               // Wh1 tf32-rounded (1xTF32 node path)
__device__ float g_Wh2hi[128 * 128];               // Wh2 tf32-rounded

// ---------------- helpers ----------------
__device__ __forceinline__ uint32_t smem_u32(const void* p) {
    uint32_t a;
    asm("{ .reg .u64 t; cvta.to.shared.u64 t, %1; cvt.u32.u64 %0, t; }" : "=r"(a) : "l"(p));
    return a;
}
__device__ __forceinline__ uint32_t rna(float x) {
    uint32_t r; asm("cvt.rna.tf32.f32 %0, %1;" : "=r"(r) : "f"(x)); return r;
}

#define CP_ASYNC(ds, gp) \
    asm volatile("cp.async.cg.shared.global [%0], [%1], 16;" :: "r"(ds), "l"(gp))
#define CP_COMMIT() asm volatile("cp.async.commit_group;" ::: "memory")
#define CP_WAIT1()  asm volatile("cp.async.wait_group 1;" ::: "memory")
#define CP_WAIT0()  asm volatile("cp.async.wait_group 0;" ::: "memory")

#define MMA_TF32(C, a0, a1, a2, a3, b0, b1) \
    asm volatile("mma.sync.aligned.m16n8k8.row.col.f32.tf32.tf32.f32 " \
        "{%0,%1,%2,%3}, {%4,%5,%6,%7}, {%8,%9}, {%0,%1,%2,%3};" \
        : "+f"((C)[0]), "+f"((C)[1]), "+f"((C)[2]), "+f"((C)[3]) \
        : "r"(a0), "r"(a1), "r"(a2), "r"(a3), "r"(b0), "r"(b1))

// =================================================================
// Fused aux: blocks [0, CV_BLOCKS) = convert (index decode + zero g_mi),
// blocks [CV_BLOCKS, CV_BLOCKS+PR_BLOCKS) = prep (weight rounding).
// =================================================================
#define CV_BLOCKS 3125
#define PR_BLOCKS 64

__global__ void aux_kernel(const void* __restrict__ ei,
                           const float* __restrict__ W1, const float* __restrict__ W2,
                           const float* __restrict__ Wh1, const float* __restrict__ Wh2) {
    const int tid = threadIdx.x;
    if (blockIdx.x < CV_BLOCKS) {
        // ---------------- convert part ----------------
        __shared__ int s64;
        if (tid == 0) {
            const int* p = (const int*)ei;
            int all0 = 1;
            for (int s = 0; s < 256; s++)
                if (p[2 * s + 1] != 0) { all0 = 0; break; }
            s64 = all0;
        }
        __syncthreads();
        int i = blockIdx.x * 256 + tid;
        if (i < N_EDGES) {
            if (s64) {
                const long long* p = (const long long*)ei;
                g_src[i] = (int)p[i];
                g_dst[i] = (int)p[N_EDGES + i];
            } else {
                const int* p = (const int*)ei;
                g_src[i] = p[i];
                g_dst[i] = p[N_EDGES + i];
            }
        }
        size_t n4 = (size_t)N_NODES * HID / 4;
        float4 z = make_float4(0.f, 0.f, 0.f, 0.f);
        for (size_t j = (size_t)blockIdx.x * 256 + tid; j < n4;
             j += (size_t)CV_BLOCKS * 256)
            ((float4*)g_mi)[j] = z;
    } else {
        // ---------------- prep part (hi-only node weights) ----------------
        int t = (blockIdx.x - CV_BLOCKS) * 256 + tid;
        int stride = PR_BLOCKS * 256;
        for (int i = t; i < 288 * 128; i += stride)
            g_W1r[i] = __uint_as_float(rna(W1[i]));
        for (int i = t; i < 128 * 128; i += stride)
            g_W2r[i] = __uint_as_float(rna(W2[i]));
        for (int i = t; i < 256 * 128; i += stride)
            g_Wh1hi[i] = __uint_as_float(rna(Wh1[i]));
        for (int i = t; i < 128 * 128; i += stride)
            g_Wh2hi[i] = __uint_as_float(rna(Wh2[i]));
    }
}

// =================================================================
// Precompute P = h @ [We1_a | We1_b]  (50k x 128 x 256, tf32 mma)
// =================================================================
#define GP_SMEM 98304

__global__ __launch_bounds__(256) void gemm_P(const float* __restrict__ h) {
    extern __shared__ char sm[];
    const uint32_t smb = smem_u32(sm);
    const int tid = threadIdx.x, lane = tid & 31, wid = tid >> 5;
    const int g = lane >> 2, t4 = lane & 3;
    const int m0 = (wid >> 2) * 64, n0 = (wid & 3) * 64;
    const int r0 = blockIdx.x * 128;

    auto issue_x = [&](int ch, int b) {
        uint32_t xb = smb + b * 16384;
#pragma unroll
        for (int i = 0; i < 4; i++) {
            int f = tid + i * 256;
            int row = f >> 3, q = f & 7;
            int gr = r0 + row; if (gr >= N_NODES) gr = 0;
            const float* gp = h + (size_t)gr * DNODE + ch * 32 + q * 4;
            uint32_t ds = xb + 4u * (uint32_t)(row * 32 + ((4 * q) ^ (4 * (row & 7))));
            CP_ASYNC(ds, gp);
        }
    };
    auto issue_w = [&](int ch, int b) {
        uint32_t wb = smb + 32768 + b * 32768;
#pragma unroll
        for (int i = 0; i < 8; i++) {
            int f = tid + i * 256;
            int k = f >> 6, n4 = f & 63;
            int n = 4 * n4;
            const float* gp = (n < 128)
                ? g_W1r + (size_t)(ch * 32 + k) * 128 + n
                : g_W1r + (size_t)(128 + ch * 32 + k) * 128 + (n - 128);
            uint32_t ds = wb + 4u * (uint32_t)(k * 256 + (n ^ (8 * (k & 3))));
            CP_ASYNC(ds, gp);
        }
    };

    float c[4][8][4];
#pragma unroll
    for (int mf = 0; mf < 4; mf++)
#pragma unroll
        for (int nf = 0; nf < 8; nf++)
#pragma unroll
            for (int j = 0; j < 4; j++) c[mf][nf][j] = 0.0f;

    issue_x(0, 0); issue_w(0, 0); CP_COMMIT();
    for (int ch = 0; ch < 4; ch++) {
        CP_WAIT0();
        __syncthreads();
        if (ch < 3) {
            issue_x(ch + 1, (ch + 1) & 1);
            issue_w(ch + 1, (ch + 1) & 1);
            CP_COMMIT();
        }
        const uint32_t* Xw = (const uint32_t*)sm + (ch & 1) * 4096;
        const uint32_t* Ww = (const uint32_t*)(sm + 32768) + (ch & 1) * 8192;
#pragma unroll
        for (int s = 0; s < 4; s++) {
            const int kb = 8 * s + t4;
            uint32_t b0r[8], b1r[8];
#pragma unroll
            for (int nf = 0; nf < 8; nf++) {
                int wc = (n0 + 8 * nf + g) ^ (8 * t4);
                b0r[nf] = Ww[kb * 256 + wc];
                b1r[nf] = Ww[(kb + 4) * 256 + wc];
            }
#pragma unroll
            for (int mf = 0; mf < 4; mf++) {
                int base = (m0 + mf * 16 + g) * 32;
                uint32_t a0 = Xw[base + (kb ^ (4 * g))];
                uint32_t a1 = Xw[base + 8 * 32 + (kb ^ (4 * g))];
                uint32_t a2 = Xw[base + ((kb + 4) ^ (4 * g))];
                uint32_t a3 = Xw[base + 8 * 32 + ((kb + 4) ^ (4 * g))];
#pragma unroll
                for (int nf = 0; nf < 8; nf++)
                    MMA_TF32(c[mf][nf], a0, a1, a2, a3, b0r[nf], b1r[nf]);
            }
        }
    }

#pragma unroll
    for (int mf = 0; mf < 4; mf++) {
        int r = m0 + mf * 16 + g;
#pragma unroll
        for (int nf = 0; nf < 8; nf++) {
            int col = n0 + 8 * nf + 2 * t4;
            if (r0 + r < N_NODES)
                *(float2*)(g_P + (size_t)(r0 + r) * 256 + col) =
                    make_float2(c[mf][nf][0], c[mf][nf][1]);
            if (r0 + r + 8 < N_NODES)
                *(float2*)(g_P + (size_t)(r0 + r + 8) * 256 + col) =
                    make_float2(c[mf][nf][2], c[mf][nf][3]);
        }
    }
}

// =================================================================
// Edge kernel (verbatim R11/R15 — converged optimum)
// =================================================================
#define EDGE_SMEM 100352

__global__ __launch_bounds__(256, 2) void edge_kernel_m(
    const float* __restrict__ ea,
    const float* __restrict__ b1g, const float* __restrict__ b2g)
{
    extern __shared__ char sm[];
    const uint32_t smb = smem_u32(sm);
    float* Ys  = (float*)sm;
    float* sb1 = (float*)(sm + 98304);
    float* sb2 = (float*)(sm + 98816);
    int*   sSrc = (int*)(sm + 99328);
    int*   sDst = (int*)(sm + 99840);

    const int tid  = threadIdx.x;
    const int lane = tid & 31, wid = tid >> 5;
    const int g    = lane >> 2, t4 = lane & 3;
    const int m0   = (wid >> 1) * 32;
    const int n0   = (wid & 1) * 64;
    const int e0   = blockIdx.x * 128;

    if (tid < 128) {
        sb1[tid] = b1g[tid];
        sb2[tid] = b2g[tid];
        sSrc[tid] = g_src[e0 + tid];
        sDst[tid] = g_dst[e0 + tid];
    }

    auto issue_w = [&](const float* W, int ch, int wb) {
        uint32_t wbase = smb + 65536 + wb * 16384;
#pragma unroll
        for (int i = 0; i < 4; i++) {
            int f = tid + i * 256;
            int k = f >> 5, n4 = f & 31;
            const float* gp = W + (size_t)(ch * 32 + k) * 128 + n4 * 4;
            uint32_t ds = wbase + 4u * (uint32_t)(k * 128 + ((4 * n4) ^ (8 * (k & 3))));
            CP_ASYNC(ds, gp);
        }
    };

    // group A: ea chunk + W1e (buf0)
#pragma unroll
    for (int i = 0; i < 4; i++) {
        int f = tid + i * 256;
        int row = f >> 3, q = f & 7;
        const float* gp = ea + (size_t)(e0 + row) * DEDGE + q * 4;
        uint32_t ds = smb + 4u * (uint32_t)(row * 32 + ((4 * q) ^ (4 * (row & 7))));
        CP_ASYNC(ds, gp);
    }
    issue_w(g_W1r, 8, 0);
    CP_COMMIT();
    // group B: W2 chunk0 (buf1) — prefetched across phase 1 + epilogue
    issue_w(g_W2r, 0, 1);
    CP_COMMIT();

    float c[2][8][4];
#pragma unroll
    for (int mf = 0; mf < 2; mf++)
#pragma unroll
        for (int nf = 0; nf < 8; nf++)
#pragma unroll
            for (int j = 0; j < 4; j++) c[mf][nf][j] = 0.0f;

    auto compute = [&](const uint32_t* Xw, int rstride, int cofs, const uint32_t* Ww) {
#pragma unroll
        for (int s = 0; s < 4; s++) {
            const int kb = 8 * s + t4;
            uint32_t b0r[8], b1r[8];
#pragma unroll
            for (int nf = 0; nf < 8; nf++) {
                int wc = (n0 + 8 * nf + g) ^ (8 * t4);
                b0r[nf] = Ww[kb * 128 + wc];
                b1r[nf] = Ww[(kb + 4) * 128 + wc];
            }
#pragma unroll
            for (int mf = 0; mf < 2; mf++) {
                int base = (m0 + mf * 16 + g) * rstride + cofs;
                uint32_t a0 = Xw[base + (kb ^ (4 * g))];
                uint32_t a1 = Xw[base + 8 * rstride + (kb ^ (4 * g))];
                uint32_t a2 = Xw[base + ((kb + 4) ^ (4 * g))];
                uint32_t a3 = Xw[base + 8 * rstride + ((kb + 4) ^ (4 * g))];
#pragma unroll
                for (int nf = 0; nf < 8; nf++)
                    MMA_TF32(c[mf][nf], a0, a1, a2, a3, b0r[nf], b1r[nf]);
            }
        }
    };

    // ======== phase 1: T = ea @ We1_e (K=32, W1e @ buf0) ========
    CP_WAIT1();
    __syncthreads();
    compute((const uint32_t*)sm, 32, 0, (const uint32_t*)(sm + 65536));
    __syncthreads();

    // group C: W2 chunk1 -> buf0 (overlaps epilogue + P-merge)
    issue_w(g_W2r, 1, 0);
    CP_COMMIT();

    // epilogue A: write raw T into Ys (swizzled), zero accumulators
#pragma unroll
    for (int mf = 0; mf < 2; mf++) {
        int r0r = m0 + mf * 16 + g;
#pragma unroll
        for (int nf = 0; nf < 8; nf++) {
            int cc = n0 + 8 * nf + 2 * t4;
            int w = (cc & ~31) + ((cc & 31) ^ (4 * g));
            *(float2*)&Ys[r0r * 128 + w]       = make_float2(c[mf][nf][0], c[mf][nf][1]);
            *(float2*)&Ys[(r0r + 8) * 128 + w] = make_float2(c[mf][nf][2], c[mf][nf][3]);
#pragma unroll
            for (int j = 0; j < 4; j++) c[mf][nf][j] = 0.0f;
        }
    }
    __syncthreads();

    // P-merge: Y = relu(T + P[src].lo + P[dst].hi + b1)   (row-major float4)
#pragma unroll 4
    for (int i = 0; i < 16; i++) {
        int f = tid + i * 256;
        int row = f >> 5, c4 = f & 31;
        int w = row * 128 + (c4 >> 3) * 32 + ((4 * (c4 & 7)) ^ (4 * (row & 7)));
        float4 t = *(const float4*)&Ys[w];
        float4 ps = *(const float4*)(g_P + (size_t)sSrc[row] * 256 + 4 * c4);
        float4 pd = *(const float4*)(g_P + (size_t)sDst[row] * 256 + 128 + 4 * c4);
        float4 b = *(const float4*)&sb1[4 * c4];
        float4 y;
        y.x = fmaxf(t.x + ps.x + pd.x + b.x, 0.0f);
        y.y = fmaxf(t.y + ps.y + pd.y + b.y, 0.0f);
        y.z = fmaxf(t.z + ps.z + pd.z + b.z, 0.0f);
        y.w = fmaxf(t.w + ps.w + pd.w + b.w, 0.0f);
        *(float4*)&Ys[w] = y;
    }

    // ======== phase 2: K=128, chunks 0..3, buffers 1,0,1,0 ========
    CP_WAIT1();
    __syncthreads();
    compute((const uint32_t*)sm, 128, 0, (const uint32_t*)(sm + 65536) + 4096);
    CP_WAIT0();
    __syncthreads();
    issue_w(g_W2r, 2, 1); CP_COMMIT();
    compute((const uint32_t*)sm, 128, 32, (const uint32_t*)(sm + 65536));
    CP_WAIT0();
    __syncthreads();
    issue_w(g_W2r, 3, 0); CP_COMMIT();
    compute((const uint32_t*)sm, 128, 64, (const uint32_t*)(sm + 65536) + 4096);
    CP_WAIT0();
    __syncthreads();
    compute((const uint32_t*)sm, 128, 96, (const uint32_t*)(sm + 65536));
    __syncthreads();

    // stage messages (+bias b2) into Ys
#pragma unroll
    for (int mf = 0; mf < 2; mf++) {
        int r0r = m0 + mf * 16 + g;
#pragma unroll
        for (int nf = 0; nf < 8; nf++) {
            int cc = n0 + 8 * nf + 2 * t4;
            float bb0 = sb2[cc], bb1 = sb2[cc + 1];
            int w = (cc & ~31) + ((cc & 31) ^ (4 * g));
            *(float2*)&Ys[r0r * 128 + w] =
                make_float2(c[mf][nf][0] + bb0, c[mf][nf][1] + bb1);
            *(float2*)&Ys[(r0r + 8) * 128 + w] =
                make_float2(c[mf][nf][2] + bb0, c[mf][nf][3] + bb1);
        }
    }
    __syncthreads();

    // coalesced vectorized scatter-add
#pragma unroll 4
    for (int i = 0; i < 16; i++) {
        int f = tid + i * 256;
        int row = f >> 5, c4 = f & 31;
        int w = row * 128 + (c4 >> 3) * 32 + ((4 * (c4 & 7)) ^ (4 * (row & 7)));
        float4 v = *(const float4*)&Ys[w];
        float* gp = g_mi + (size_t)sDst[row] * HID + 4 * c4;
        asm volatile("red.global.add.v4.f32 [%0], {%1,%2,%3,%4};"
                     :: "l"(gp), "f"(v.x), "f"(v.y), "f"(v.z), "f"(v.w) : "memory");
    }
}

// =================================================================
// Node MLP via 1xTF32 mma: out ≈ rna(x) @ rna(w).
// Error vs fp32: x_lo@w + x@w_lo (~3-4e-4 combined), on top of the
// edge path's 7.23e-4 -> predicted total ~8.0-8.6e-4 (< 1e-3 gate).
// Half the MMAs of the R16 node kernel; same smem/schedule.
// smem: Ys 32KB @0 (X chunks overlay [0,16384)), Whi 2x16KB @32768,
//       sb1@65536, sb2@66048
// =================================================================
#define NODE_SMEM 66560

__global__ __launch_bounds__(256, 2) void node_kernel_m(
    const float* __restrict__ h,
    const float* __restrict__ b1g, const float* __restrict__ b2g,
    float* __restrict__ out)
{
    extern __shared__ char sm[];
    const uint32_t smb = smem_u32(sm);
    float* Ys  = (float*)sm;
    float* sb1 = (float*)(sm + 65536);
    float* sb2 = (float*)(sm + 66048);

    const int tid  = threadIdx.x;
    const int lane = tid & 31, wid = tid >> 5;
    const int g    = lane >> 2, t4 = lane & 3;
    const int m0   = (wid >> 1) * 16;
    const int n0   = (wid & 1) * 64;
    const int r0   = blockIdx.x * 64;

    if (tid < 128) { sb1[tid] = b1g[tid]; sb2[tid] = b2g[tid]; }

    auto issue_x = [&](int ch, int b) {
        uint32_t xb = smb + b * 8192;
#pragma unroll
        for (int i = 0; i < 2; i++) {
            int f = tid + i * 256;
            int row = f >> 3, q = f & 7;
            int gr = r0 + row; if (gr >= N_NODES) gr = 0;
            const float* gp = (ch < 4)
                ? h    + (size_t)gr * DNODE + ch * 32 + q * 4
                : g_mi + (size_t)gr * HID   + (ch - 4) * 32 + q * 4;
            uint32_t ds = xb + 4u * (uint32_t)(row * 32 + ((4 * q) ^ (4 * (row & 7))));
            CP_ASYNC(ds, gp);
        }
    };
    auto issue_w = [&](const float* Whi, int ch, int b) {
        uint32_t base_hi = smb + 32768 + b * 16384;
#pragma unroll
        for (int i = 0; i < 4; i++) {
            int f = tid + i * 256;
            int k = f >> 5, n4 = f & 31;
            uint32_t off = 4u * (uint32_t)(k * 128 + ((4 * n4) ^ (8 * (k & 3))));
            CP_ASYNC(base_hi + off, Whi + (size_t)(ch * 32 + k) * 128 + n4 * 4);
        }
    };

    float c[8][4];
#pragma unroll
    for (int nf = 0; nf < 8; nf++)
#pragma unroll
        for (int j = 0; j < 4; j++) c[nf][j] = 0.0f;

    auto computeN = [&](const uint32_t* Xw, int rstride, int cofs,
                        const uint32_t* Whi) {
#pragma unroll
        for (int s = 0; s < 4; s++) {
            const int kb = 8 * s + t4;
            int base0 = (m0 + g) * rstride + cofs;
            int base1 = (m0 + 8 + g) * rstride + cofs;
            uint32_t h0 = rna(__uint_as_float(Xw[base0 + (kb ^ (4 * g))]));
            uint32_t h1 = rna(__uint_as_float(Xw[base1 + (kb ^ (4 * g))]));
            uint32_t h2 = rna(__uint_as_float(Xw[base0 + ((kb + 4) ^ (4 * g))]));
            uint32_t h3 = rna(__uint_as_float(Xw[base1 + ((kb + 4) ^ (4 * g))]));
#pragma unroll
            for (int nf = 0; nf < 8; nf++) {
                int wc = (n0 + 8 * nf + g) ^ (8 * t4);
                uint32_t bh0 = Whi[kb * 128 + wc], bh1 = Whi[(kb + 4) * 128 + wc];
                MMA_TF32(c[nf], h0, h1, h2, h3, bh0, bh1);
            }
        }
    };

    // ======== layer 1: K=256, 8 chunks — one sync per chunk ========
    issue_x(0, 0); issue_w(g_Wh1hi, 0, 0); CP_COMMIT();
    for (int ch = 0; ch < 8; ch++) {
        CP_WAIT0();
        __syncthreads();
        if (ch < 7) {
            issue_x(ch + 1, (ch + 1) & 1);
            issue_w(g_Wh1hi, ch + 1, (ch + 1) & 1);
            CP_COMMIT();
        }
        computeN((const uint32_t*)sm + (ch & 1) * 2048, 32, 0,
                 (const uint32_t*)(sm + 32768 + (ch & 1) * 16384));
    }
    __syncthreads();   // last compute done before Ys (overlaps X bufs) is written

    // ---- epilogue 1: relu(x + b1) -> Ys (swizzled), zero c ----
#pragma unroll
    for (int nf = 0; nf < 8; nf++) {
        int cc = n0 + 8 * nf + 2 * t4;
        float bb0 = sb1[cc], bb1 = sb1[cc + 1];
        int w = (cc & ~31) + ((cc & 31) ^ (4 * g));
        *(float2*)&Ys[(m0 + g) * 128 + w] =
            make_float2(fmaxf(c[nf][0] + bb0, 0.0f), fmaxf(c[nf][1] + bb1, 0.0f));
        *(float2*)&Ys[(m0 + 8 + g) * 128 + w] =
            make_float2(fmaxf(c[nf][2] + bb0, 0.0f), fmaxf(c[nf][3] + bb1, 0.0f));
#pragma unroll
        for (int j = 0; j < 4; j++) c[nf][j] = 0.0f;
    }
    issue_w(g_Wh2hi, 0, 0); CP_COMMIT();

    // ======== layer 2: K=128, 4 chunks — one sync per chunk ========
    for (int ch = 0; ch < 4; ch++) {
        CP_WAIT0();
        __syncthreads();   // ch0's sync also publishes epilogue Ys writes
        if (ch < 3) {
            issue_w(g_Wh2hi, ch + 1, (ch + 1) & 1);
            CP_COMMIT();
        }
        computeN((const uint32_t*)sm, 128, ch * 32,
                 (const uint32_t*)(sm + 32768 + (ch & 1) * 16384));
    }

    // ---- store out = c + b2 (own accumulators only) ----
#pragma unroll
    for (int nf = 0; nf < 8; nf++) {
        int cc = n0 + 8 * nf + 2 * t4;
        float bb0 = sb2[cc], bb1 = sb2[cc + 1];
        int ra = r0 + m0 + g, rb = ra + 8;
        if (ra < N_NODES)
            *(float2*)(out + (size_t)ra * 128 + cc) =
                make_float2(c[nf][0] + bb0, c[nf][1] + bb1);
        if (rb < N_NODES)
            *(float2*)(out + (size_t)rb * 128 + cc) =
                make_float2(c[nf][2] + bb0, c[nf][3] + bb1);
    }
}

// =================================================================
extern "C" void kernel_launch(void* const* d_in, const int* in_sizes, int n_in,
                              void* d_out, int out_size) {
    const float* h   = (const float*)d_in[0];
    const void*  ei  = d_in[1];
    const float* ea  = (const float*)d_in[2];
    const float* We1 = (const float*)d_in[3];
    const float* be1 = (const float*)d_in[4];
    const float* We2 = (const float*)d_in[5];
    const float* be2 = (const float*)d_in[6];
    const float* Wh1 = (const float*)d_in[7];
    const float* bh1 = (const float*)d_in[8];
    const float* Wh2 = (const float*)d_in[9];
    const float* bh2 = (const float*)d_in[10];
    float* out = (float*)d_out;

    cudaFuncSetAttribute(edge_kernel_m, cudaFuncAttributeMaxDynamicSharedMemorySize, EDGE_SMEM);
    cudaFuncSetAttribute(gemm_P, cudaFuncAttributeMaxDynamicSharedMemorySize, GP_SMEM);
    cudaFuncSetAttribute(node_kernel_m, cudaFuncAttributeMaxDynamicSharedMemorySize, NODE_SMEM);

    aux_kernel<<<CV_BLOCKS + PR_BLOCKS, 256>>>(ei, We1, We2, Wh1, Wh2);  // convert || prep
    gemm_P<<<(N_NODES + 127) / 128, 256, GP_SMEM>>>(h);
    edge_kernel_m<<<N_EDGES / 128, 256, EDGE_SMEM>>>(ea, be1, be2);
    node_kernel_m<<<(N_NODES + 63) / 64, 256, NODE_SMEM>>>(h, bh1, bh2, out);
}